// round 1
// baseline (speedup 1.0000x reference)
#include <cuda_runtime.h>
#include <cuda_bf16.h>
#include <cstdint>

// Problem constants
#define BATCH 32
#define NN    512       // nodes
#define NF    128       // input features
#define FH    64        // hidden per head
#define NH    8         // heads
#define NC    16        // classes
#define BH    (BATCH*NH)

// ------------------------- scratch (device globals, no allocs) -------------
__device__ float    g_h[BATCH*NH*NN*FH];     // head projections [b][h][n][64]
__device__ float    g_f1[BATCH*NH*NN];
__device__ float    g_f2[BATCH*NH*NN];
__device__ unsigned g_adjbits[BATCH*NN*16];  // 512 bits per row
__device__ float    g_xcat[BATCH*NN*NH*FH];  // layer-1 output (concat) [b][n][512]
__device__ float    g_h2[BATCH*NN*NC];       // output projection
__device__ float    g_f1o[BATCH*NN];
__device__ float    g_f2o[BATCH*NN];

// ------------------------- kernel 1: adjacency -> bitmask ------------------
__global__ void adjbits_kernel(const int* __restrict__ adj) {
    int w = threadIdx.x >> 5, lane = threadIdx.x & 31;
    int row = blockIdx.x * 8 + w;              // row in [0, B*N)
    const int* ap = adj + (size_t)row * NN;
    unsigned* op = g_adjbits + row * 16;
#pragma unroll
    for (int it = 0; it < 16; ++it) {
        int v = ap[it * 32 + lane];
        unsigned m = __ballot_sync(0xffffffffu, v > 0);
        if (lane == 0) op[it] = m;
    }
}

// ------------------------- kernel 2: head projection GEMM ------------------
// h[b,h,n,o] = sum_f x[b,n,f] * W[h,f,o].  64-row x 64-col tile per block.
__global__ void __launch_bounds__(256) gemm_heads(const float* __restrict__ x,
                                                  const float* __restrict__ Wh) {
    extern __shared__ float sm[];
    float* xT = sm;             // [128][68] (k-major, row padded)
    float* Ws = sm + 128 * 68;  // [128][68]
    int head = blockIdx.y, b = blockIdx.z;
    int n0 = blockIdx.x * 64;
    int t = threadIdx.x;

    const float* xp = x + ((size_t)b * NN + n0) * NF;
    for (int idx = t; idx < 64 * 128; idx += 256) {
        int r = idx >> 7, f = idx & 127;
        xT[f * 68 + r] = xp[idx];
    }
    const float* Wp = Wh + head * NF * FH;
    for (int idx = t; idx < 128 * 64; idx += 256) {
        int f = idx >> 6, o = idx & 63;
        Ws[f * 68 + o] = Wp[idx];
    }
    __syncthreads();

    int tx = t & 15, ty = t >> 4;
    float acc[4][4] = {};
#pragma unroll 4
    for (int k = 0; k < 128; ++k) {
        float4 av = *(const float4*)&xT[k * 68 + ty * 4];
        float4 bv = *(const float4*)&Ws[k * 68 + tx * 4];
        float ar[4] = {av.x, av.y, av.z, av.w};
        float br[4] = {bv.x, bv.y, bv.z, bv.w};
#pragma unroll
        for (int i = 0; i < 4; ++i)
#pragma unroll
            for (int j = 0; j < 4; ++j) acc[i][j] = fmaf(ar[i], br[j], acc[i][j]);
    }
    float* hp = g_h + (((size_t)b * NH + head) * NN + n0) * FH;
#pragma unroll
    for (int i = 0; i < 4; ++i) {
        float4 v = make_float4(acc[i][0], acc[i][1], acc[i][2], acc[i][3]);
        *(float4*)&hp[(ty * 4 + i) * FH + tx * 4] = v;
    }
}

// ------------------------- kernel 3: f1/f2 per head ------------------------
__global__ void f12_heads(const float* __restrict__ a1, const float* __restrict__ a2) {
    int bh = blockIdx.x;
    int head = bh & 7;
    int w = threadIdx.x >> 5, lane = threadIdx.x & 31;
    float2 a1v = *(const float2*)&a1[head * FH + 2 * lane];
    float2 a2v = *(const float2*)&a2[head * FH + 2 * lane];
    const float* hp = g_h + (size_t)bh * NN * FH;
    for (int n = w; n < NN; n += 8) {
        float2 hv = *(const float2*)&hp[n * FH + 2 * lane];
        float s1 = hv.x * a1v.x + hv.y * a1v.y;
        float s2 = hv.x * a2v.x + hv.y * a2v.y;
#pragma unroll
        for (int o = 16; o; o >>= 1) {
            s1 += __shfl_xor_sync(0xffffffffu, s1, o);
            s2 += __shfl_xor_sync(0xffffffffu, s2, o);
        }
        if (lane == 0) {
            g_f1[bh * NN + n] = s1;
            g_f2[bh * NN + n] = s2;
        }
    }
}

// ------------------------- kernel 4: fused attention -----------------------
// One block per (b,head) [layer1] or per b [layer2]. h tile + f2 in smem,
// per-warp p buffer (4 rows register-blocked). Scores are separable:
// e_ij = lrelu(f1_i + f2_j), masked, softmax over j, out = P @ h.
template <bool L1>
__global__ void __launch_bounds__(256) attn_kernel(float* __restrict__ out_l2) {
    constexpr int F = L1 ? FH : NC;
    extern __shared__ float sm[];
    float* hs = sm;                 // [512][F]
    float* f2s = hs + NN * F;       // [512]
    float* ps = f2s + NN;           // [8][4][512]

    int blk = blockIdx.x;
    int b = L1 ? (blk >> 3) : blk;
    const float* hp  = (L1 ? g_h  : g_h2)  + (size_t)blk * NN * F;
    const float* f1p = (L1 ? g_f1 : g_f1o) + blk * NN;
    const float* f2p = (L1 ? g_f2 : g_f2o) + blk * NN;
    const unsigned* ab = g_adjbits + (size_t)b * NN * 16;

    int t = threadIdx.x, w = t >> 5, lane = t & 31;

    {   // stage h and f2
        const float4* hp4 = (const float4*)hp;
        float4* hs4 = (float4*)hs;
        for (int i = t; i < NN * F / 4; i += 256) hs4[i] = hp4[i];
        for (int i = t; i < NN; i += 256) f2s[i] = f2p[i];
    }
    __syncthreads();

    float* pw = ps + w * 4 * NN;

    for (int pass = 0; pass < 16; ++pass) {
        int r0 = pass * 32 + w * 4;
        float inv[4];
        __syncwarp();
        // ---- scores + softmax weights for 4 rows ----
#pragma unroll
        for (int r = 0; r < 4; ++r) {
            int row = r0 + r;
            float f1r = __ldg(&f1p[row]);
            const unsigned* abr = ab + row * 16;
            float ev[16];
            float mx = -3.4e38f;
#pragma unroll
            for (int it = 0; it < 16; ++it) {
                float e = f1r + f2s[lane + 32 * it];
                e = e > 0.f ? e : 0.2f * e;
                e = ((abr[it] >> lane) & 1u) ? e : -9e15f;
                ev[it] = e;
                mx = fmaxf(mx, e);
            }
#pragma unroll
            for (int o = 16; o; o >>= 1) mx = fmaxf(mx, __shfl_xor_sync(0xffffffffu, mx, o));
            float s = 0.f;
#pragma unroll
            for (int it = 0; it < 16; ++it) {
                float p = __expf(ev[it] - mx);
                s += p;
                pw[r * NN + lane + 32 * it] = p;
            }
#pragma unroll
            for (int o = 16; o; o >>= 1) s += __shfl_xor_sync(0xffffffffu, s, o);
            inv[r] = 1.f / s;
        }
        __syncwarp();

        // ---- P @ h for 4 rows ----
        if (L1) {
            const float2* h2 = (const float2*)hs;   // [512][32] float2
            float2 a0 = {0, 0}, a1 = {0, 0}, a2 = {0, 0}, a3 = {0, 0};
#pragma unroll 4
            for (int j = 0; j < NN; ++j) {
                float2 hv = h2[j * 32 + lane];
                float p0 = pw[j], p1 = pw[NN + j], p2 = pw[2 * NN + j], p3 = pw[3 * NN + j];
                a0.x = fmaf(p0, hv.x, a0.x); a0.y = fmaf(p0, hv.y, a0.y);
                a1.x = fmaf(p1, hv.x, a1.x); a1.y = fmaf(p1, hv.y, a1.y);
                a2.x = fmaf(p2, hv.x, a2.x); a2.y = fmaf(p2, hv.y, a2.y);
                a3.x = fmaf(p3, hv.x, a3.x); a3.y = fmaf(p3, hv.y, a3.y);
            }
            int head = blk & 7;
            float2 accs[4] = {a0, a1, a2, a3};
#pragma unroll
            for (int r = 0; r < 4; ++r) {
                float vx = accs[r].x * inv[r];
                float vy = accs[r].y * inv[r];
                vx = vx > 0.f ? vx : (__expf(vx) - 1.f);   // ELU (concat layer)
                vy = vy > 0.f ? vy : (__expf(vy) - 1.f);
                float* op = g_xcat + ((size_t)b * NN + (r0 + r)) * (NH * FH) + head * FH + 2 * lane;
                *(float2*)op = make_float2(vx, vy);
            }
        } else {
            float acc[4] = {0, 0, 0, 0};
            int c = lane & 15;
            int jb = (lane >> 4) * 256;      // split j-range across half-warps
            for (int j = jb; j < jb + 256; ++j) {
                float hv = hs[j * NC + c];
                acc[0] = fmaf(pw[j], hv, acc[0]);
                acc[1] = fmaf(pw[NN + j], hv, acc[1]);
                acc[2] = fmaf(pw[2 * NN + j], hv, acc[2]);
                acc[3] = fmaf(pw[3 * NN + j], hv, acc[3]);
            }
#pragma unroll
            for (int r = 0; r < 4; ++r) acc[r] += __shfl_xor_sync(0xffffffffu, acc[r], 16);
            if (lane < 16) {
#pragma unroll
                for (int r = 0; r < 4; ++r)
                    out_l2[((size_t)b * NN + (r0 + r)) * NC + c] = acc[r] * inv[r];
            }
        }
    }
}

// ------------------------- kernel 5: output projection GEMM ----------------
__global__ void __launch_bounds__(256) gemm_out(const float* __restrict__ Wout) {
    __shared__ float Ws[512 * 17];
    int b = blockIdx.x, rt = blockIdx.y;
    int t = threadIdx.x;
    for (int idx = t; idx < 512 * 16; idx += 256) {
        int k = idx >> 4, c = idx & 15;
        Ws[k * 17 + c] = Wout[idx];
    }
    __syncthreads();
    int w = t >> 5, lane = t & 31;
    int c = lane & 15;
    int k0 = (lane >> 4) * 256;
    for (int rr = w; rr < 64; rr += 8) {
        int row = rt * 64 + rr;
        const float* xp = g_xcat + ((size_t)b * NN + row) * 512;
        float acc = 0.f;
#pragma unroll 8
        for (int kk = 0; kk < 256; ++kk) {
            float xv = __ldg(&xp[k0 + kk]);
            acc = fmaf(xv, Ws[(k0 + kk) * 17 + c], acc);
        }
        acc += __shfl_xor_sync(0xffffffffu, acc, 16);
        if (lane < 16) g_h2[((size_t)b * NN + row) * NC + c] = acc;
    }
}

// ------------------------- kernel 6: f1/f2 for output layer ----------------
__global__ void f12_out(const float* __restrict__ a1o, const float* __restrict__ a2o) {
    int b = blockIdx.x;
    int n = threadIdx.x;
    const float* hp = g_h2 + ((size_t)b * NN + n) * NC;
    float s1 = 0.f, s2 = 0.f;
#pragma unroll
    for (int c = 0; c < NC; ++c) {
        float v = hp[c];
        s1 = fmaf(v, __ldg(&a1o[c]), s1);
        s2 = fmaf(v, __ldg(&a2o[c]), s2);
    }
    g_f1o[b * NN + n] = s1;
    g_f2o[b * NN + n] = s2;
}

// ------------------------- launch ------------------------------------------
extern "C" void kernel_launch(void* const* d_in, const int* in_sizes, int n_in,
                              void* d_out, int out_size) {
    const float* x    = (const float*)d_in[0];
    const int*   adj  = (const int*)  d_in[1];
    const float* Wh   = (const float*)d_in[2];
    const float* a1h  = (const float*)d_in[3];
    const float* a2h  = (const float*)d_in[4];
    const float* Wout = (const float*)d_in[5];
    const float* a1o  = (const float*)d_in[6];
    const float* a2o  = (const float*)d_in[7];
    float* out = (float*)d_out;

    const int smem_gemm1 = 2 * 128 * 68 * 4;                       // 69632
    const int smem_attn1 = (NN * FH + NN + 8 * 4 * NN) * 4;        // 198656
    const int smem_attn2 = (NN * NC + NN + 8 * 4 * NN) * 4;        // 100352

    cudaFuncSetAttribute(gemm_heads, cudaFuncAttributeMaxDynamicSharedMemorySize, smem_gemm1);
    cudaFuncSetAttribute(attn_kernel<true>, cudaFuncAttributeMaxDynamicSharedMemorySize, smem_attn1);
    cudaFuncSetAttribute(attn_kernel<false>, cudaFuncAttributeMaxDynamicSharedMemorySize, smem_attn2);

    adjbits_kernel<<<BATCH * NN / 8, 256>>>(adj);
    gemm_heads<<<dim3(8, NH, BATCH), 256, smem_gemm1>>>(x, Wh);
    f12_heads<<<BH, 256>>>(a1h, a2h);
    attn_kernel<true><<<BH, 256, smem_attn1>>>(nullptr);
    gemm_out<<<dim3(BATCH, 8), 256>>>(Wout);
    f12_out<<<BATCH, NN>>>(a1o, a2o);
    attn_kernel<false><<<BATCH, 256, smem_attn2>>>(out);
}

// round 2
// speedup vs baseline: 1.6841x; 1.6841x over previous
#include <cuda_runtime.h>
#include <cuda_bf16.h>
#include <cstdint>

// Problem constants
#define BATCH 32
#define NN    512       // nodes
#define NF    128       // input features
#define FH    64        // hidden per head
#define NH    8         // heads
#define NC    16        // classes
#define BH    (BATCH*NH)

// ------------------------- scratch (device globals, no allocs) -------------
__device__ float    g_h[BATCH*NH*NN*FH];     // head projections [b][h][n][64]
__device__ float    g_f1[BATCH*NH*NN];
__device__ float    g_f2[BATCH*NH*NN];
__device__ unsigned g_adjbits[BATCH*NN*16];  // 512 bits per row
__device__ float    g_xcat[BATCH*NN*NH*FH];  // layer-1 output (concat) [b][n][512]
__device__ float    g_h2[BATCH*NN*NC];       // output projection
__device__ float    g_f1o[BATCH*NN];
__device__ float    g_f2o[BATCH*NN];

// ------------------------- helpers -----------------------------------------
__device__ __forceinline__ float to_tf32(float v) {
    uint32_t b;
    asm("cvt.rna.tf32.f32 %0, %1;" : "=r"(b) : "f"(v));
    return __uint_as_float(b);
}

__device__ __forceinline__ void mma_tf32(float d[4], const uint32_t a[4], const uint32_t b[2]) {
    asm volatile(
        "mma.sync.aligned.m16n8k8.row.col.f32.tf32.tf32.f32 "
        "{%0,%1,%2,%3}, {%4,%5,%6,%7}, {%8,%9}, {%0,%1,%2,%3};"
        : "+f"(d[0]), "+f"(d[1]), "+f"(d[2]), "+f"(d[3])
        : "r"(a[0]), "r"(a[1]), "r"(a[2]), "r"(a[3]), "r"(b[0]), "r"(b[1]));
}

// ------------------------- kernel 1: adjacency -> bitmask ------------------
__global__ void adjbits_kernel(const int* __restrict__ adj) {
    int w = threadIdx.x >> 5, lane = threadIdx.x & 31;
    int row = blockIdx.x * 8 + w;              // row in [0, B*N)
    const int* ap = adj + (size_t)row * NN;
    unsigned* op = g_adjbits + row * 16;
#pragma unroll
    for (int it = 0; it < 16; ++it) {
        int v = ap[it * 32 + lane];
        unsigned m = __ballot_sync(0xffffffffu, v > 0);
        if (lane == 0) op[it] = m;
    }
}

// ------------------------- kernel 2: head projection GEMM (tf32 MMA) -------
// h[b,h,n,o] = sum_f x[b,n,f] * W[h,f,o].  64-row x 64-col tile per block.
#define XS_STRIDE 136   // 128 + 8 (=> gid*8+tig distinct mod 32)
#define WS_STRIDE 72    // 64 + 8
__global__ void __launch_bounds__(256) gemm_heads(const float* __restrict__ x,
                                                  const float* __restrict__ Wh) {
    extern __shared__ float sm[];
    float* xs = sm;                     // [64][136]
    float* Ws = sm + 64 * XS_STRIDE;    // [128][72]
    int head = blockIdx.y, b = blockIdx.z;
    int n0 = blockIdx.x * 64;
    int t = threadIdx.x;

    const float4* xp4 = (const float4*)(x + ((size_t)b * NN + n0) * NF);
    for (int idx = t; idx < 64 * 32; idx += 256) {      // 64 rows x 32 float4
        int r = idx >> 5, c4 = idx & 31;
        float4 v = xp4[idx];
        v.x = to_tf32(v.x); v.y = to_tf32(v.y); v.z = to_tf32(v.z); v.w = to_tf32(v.w);
        *(float4*)&xs[r * XS_STRIDE + c4 * 4] = v;
    }
    const float4* Wp4 = (const float4*)(Wh + (size_t)head * NF * FH);
    for (int idx = t; idx < 128 * 16; idx += 256) {     // 128 rows x 16 float4
        int f = idx >> 4, o4 = idx & 15;
        float4 v = Wp4[idx];
        v.x = to_tf32(v.x); v.y = to_tf32(v.y); v.z = to_tf32(v.z); v.w = to_tf32(v.w);
        *(float4*)&Ws[f * WS_STRIDE + o4 * 4] = v;
    }
    __syncthreads();

    int w = t >> 5, lane = t & 31;
    int gid = lane >> 2, tig = lane & 3;
    int mt = w >> 1;                 // 0..3 (16-row m-tile)
    int nbase = (w & 1) * 32;        // 4 n-tiles of 8 cols each

    float d[4][4] = {};
    uint32_t a[4], bf[2];
#pragma unroll
    for (int kk = 0; kk < 16; ++kk) {
        int k0 = kk * 8;
        const float* pa = xs + (mt * 16 + gid) * XS_STRIDE + k0 + tig;
        a[0] = __float_as_uint(pa[0]);
        a[1] = __float_as_uint(pa[8 * XS_STRIDE]);
        a[2] = __float_as_uint(pa[4]);
        a[3] = __float_as_uint(pa[8 * XS_STRIDE + 4]);
#pragma unroll
        for (int nt = 0; nt < 4; ++nt) {
            const float* pb = Ws + (k0 + tig) * WS_STRIDE + nbase + nt * 8 + gid;
            bf[0] = __float_as_uint(pb[0]);
            bf[1] = __float_as_uint(pb[4 * WS_STRIDE]);
            mma_tf32(d[nt], a, bf);
        }
    }

    float* hp = g_h + (((size_t)b * NH + head) * NN + n0) * FH;
#pragma unroll
    for (int nt = 0; nt < 4; ++nt) {
        int col = nbase + nt * 8 + 2 * tig;
        int r0 = mt * 16 + gid;
        *(float2*)&hp[r0 * FH + col]       = make_float2(d[nt][0], d[nt][1]);
        *(float2*)&hp[(r0 + 8) * FH + col] = make_float2(d[nt][2], d[nt][3]);
    }
}

// ------------------------- kernel 3: f1/f2 per head ------------------------
__global__ void f12_heads(const float* __restrict__ a1, const float* __restrict__ a2) {
    int bh = blockIdx.x;
    int head = bh & 7;
    int w = threadIdx.x >> 5, lane = threadIdx.x & 31;
    float2 a1v = *(const float2*)&a1[head * FH + 2 * lane];
    float2 a2v = *(const float2*)&a2[head * FH + 2 * lane];
    const float* hp = g_h + (size_t)bh * NN * FH;
    for (int n = w; n < NN; n += 8) {
        float2 hv = *(const float2*)&hp[n * FH + 2 * lane];
        float s1 = hv.x * a1v.x + hv.y * a1v.y;
        float s2 = hv.x * a2v.x + hv.y * a2v.y;
#pragma unroll
        for (int o = 16; o; o >>= 1) {
            s1 += __shfl_xor_sync(0xffffffffu, s1, o);
            s2 += __shfl_xor_sync(0xffffffffu, s2, o);
        }
        if (lane == 0) {
            g_f1[bh * NN + n] = s1;
            g_f2[bh * NN + n] = s2;
        }
    }
}

// ------------------------- kernel 4: fused attention layer 1 (tf32 MMA) ----
// One block per (b,head). h staged in smem (stride 72 => conflict-free B
// frags). Loop over 16 chunks of 32 rows: compute masked-softmax P chunk
// (tf32) into smem (stride 520 => near-conflict-free A frags), then
// m16n8k8 tf32 MMAs produce P @ h, normalized + ELU epilogue.
#define HS_STRIDE 72
#define PS_STRIDE 520
__global__ void __launch_bounds__(256) attn1_kernel() {
    extern __shared__ float sm[];
    float* hs   = sm;                            // [512][72]
    float* Ps   = hs + NN * HS_STRIDE;           // [32][520]
    float* f2s  = Ps + 32 * PS_STRIDE;           // [512]
    float* invs = f2s + NN;                      // [32]

    int blk = blockIdx.x;
    int b = blk >> 3, head = blk & 7;
    const float* hp  = g_h  + (size_t)blk * NN * FH;
    const float* f1p = g_f1 + blk * NN;
    const float* f2p = g_f2 + blk * NN;
    const unsigned* ab = g_adjbits + (size_t)b * NN * 16;

    int t = threadIdx.x, w = t >> 5, lane = t & 31;
    int gid = lane >> 2, tig = lane & 3;

    {   // stage h (tf32) and f2
        const float4* hp4 = (const float4*)hp;
        for (int idx = t; idx < NN * 16; idx += 256) {
            int j = idx >> 4, c4 = idx & 15;
            float4 v = hp4[idx];
            v.x = to_tf32(v.x); v.y = to_tf32(v.y); v.z = to_tf32(v.z); v.w = to_tf32(v.w);
            *(float4*)&hs[j * HS_STRIDE + c4 * 4] = v;
        }
        for (int i = t; i < NN; i += 256) f2s[i] = f2p[i];
    }
    __syncthreads();

    int m0 = (w >> 2) * 16;          // m-tile base within chunk (0 or 16)
    int nb = (w & 3) * 16;           // two 8-col n-tiles at nb, nb+8

    for (int ch = 0; ch < 16; ++ch) {
        int r0 = ch * 32;
        // ---- scores + softmax weights for this warp's 4 rows ----
        float* pw = Ps + (w * 4) * PS_STRIDE;
#pragma unroll
        for (int r = 0; r < 4; ++r) {
            int row = r0 + w * 4 + r;
            float f1r = __ldg(&f1p[row]);
            const unsigned* abr = ab + row * 16;
            float ev[16];
            float mx = -3.4e38f;
#pragma unroll
            for (int it = 0; it < 16; ++it) {
                float e = f1r + f2s[lane + 32 * it];
                e = e > 0.f ? e : 0.2f * e;
                e = ((abr[it] >> lane) & 1u) ? e : -9e15f;
                ev[it] = e;
                mx = fmaxf(mx, e);
            }
#pragma unroll
            for (int o = 16; o; o >>= 1) mx = fmaxf(mx, __shfl_xor_sync(0xffffffffu, mx, o));
            float s = 0.f;
#pragma unroll
            for (int it = 0; it < 16; ++it) {
                float p = to_tf32(__expf(ev[it] - mx));
                s += p;
                pw[r * PS_STRIDE + lane + 32 * it] = p;
            }
#pragma unroll
            for (int o = 16; o; o >>= 1) s += __shfl_xor_sync(0xffffffffu, s, o);
            if (lane == 0) invs[w * 4 + r] = 1.f / s;
        }
        __syncthreads();

        // ---- MMA: P_chunk[32,512] @ h[512,64]; warp does 2 (16x8) tiles ----
        float d0[4] = {}, d1[4] = {};
        uint32_t a[4], bf0[2], bf1[2];
        const float* paB = Ps + (m0 + gid) * PS_STRIDE + tig;
        const float* pbB = hs + tig * HS_STRIDE + nb + gid;
#pragma unroll 8
        for (int k0 = 0; k0 < NN; k0 += 8) {
            const float* pa = paB + k0;
            a[0] = __float_as_uint(pa[0]);
            a[1] = __float_as_uint(pa[8 * PS_STRIDE]);
            a[2] = __float_as_uint(pa[4]);
            a[3] = __float_as_uint(pa[8 * PS_STRIDE + 4]);
            const float* pb = pbB + k0 * HS_STRIDE;
            bf0[0] = __float_as_uint(pb[0]);
            bf0[1] = __float_as_uint(pb[4 * HS_STRIDE]);
            bf1[0] = __float_as_uint(pb[8]);
            bf1[1] = __float_as_uint(pb[4 * HS_STRIDE + 8]);
            mma_tf32(d0, a, bf0);
            mma_tf32(d1, a, bf1);
        }

        // ---- epilogue: normalize, ELU, write to x_cat ----
        {
            float i0 = invs[m0 + gid];
            float i1 = invs[m0 + gid + 8];
            int row0 = r0 + m0 + gid;
            float* ob = g_xcat + ((size_t)b * NN) * (NH * FH) + head * FH + nb + 2 * tig;
#pragma unroll
            for (int half = 0; half < 2; ++half) {
                float* d = half ? d1 : d0;
                int coff = half * 8;
                float vx = d[0] * i0, vy = d[1] * i0;
                vx = vx > 0.f ? vx : (__expf(vx) - 1.f);
                vy = vy > 0.f ? vy : (__expf(vy) - 1.f);
                *(float2*)&ob[(size_t)row0 * (NH * FH) + coff] = make_float2(vx, vy);
                float ux = d[2] * i1, uy = d[3] * i1;
                ux = ux > 0.f ? ux : (__expf(ux) - 1.f);
                uy = uy > 0.f ? uy : (__expf(uy) - 1.f);
                *(float2*)&ob[(size_t)(row0 + 8) * (NH * FH) + coff] = make_float2(ux, uy);
            }
        }
        __syncthreads();
    }
}

// ------------------------- kernel 5: output projection GEMM ----------------
__global__ void __launch_bounds__(256) gemm_out(const float* __restrict__ Wout) {
    __shared__ float Ws[512 * 17];
    int b = blockIdx.x, rt = blockIdx.y;
    int t = threadIdx.x;
    for (int idx = t; idx < 512 * 16; idx += 256) {
        int k = idx >> 4, c = idx & 15;
        Ws[k * 17 + c] = Wout[idx];
    }
    __syncthreads();
    int w = t >> 5, lane = t & 31;
    int c = lane & 15;
    int k0 = (lane >> 4) * 256;
    for (int rr = w; rr < 64; rr += 8) {
        int row = rt * 64 + rr;
        const float* xp = g_xcat + ((size_t)b * NN + row) * 512;
        float acc = 0.f;
#pragma unroll 8
        for (int kk = 0; kk < 256; ++kk) {
            float xv = __ldg(&xp[k0 + kk]);
            acc = fmaf(xv, Ws[(k0 + kk) * 17 + c], acc);
        }
        acc += __shfl_xor_sync(0xffffffffu, acc, 16);
        if (lane < 16) g_h2[((size_t)b * NN + row) * NC + c] = acc;
    }
}

// ------------------------- kernel 6: f1/f2 for output layer ----------------
__global__ void f12_out(const float* __restrict__ a1o, const float* __restrict__ a2o) {
    int b = blockIdx.x;
    int n = threadIdx.x;
    const float* hp = g_h2 + ((size_t)b * NN + n) * NC;
    float s1 = 0.f, s2 = 0.f;
#pragma unroll
    for (int c = 0; c < NC; ++c) {
        float v = hp[c];
        s1 = fmaf(v, __ldg(&a1o[c]), s1);
        s2 = fmaf(v, __ldg(&a2o[c]), s2);
    }
    g_f1o[b * NN + n] = s1;
    g_f2o[b * NN + n] = s2;
}

// ------------------------- kernel 7: output attention (scalar, row-split) --
__global__ void __launch_bounds__(256) attn_out(float* __restrict__ out_l2) {
    extern __shared__ float sm[];
    float* hs = sm;                 // [512][16]
    float* f2s = hs + NN * NC;      // [512]
    float* ps = f2s + NN;           // [8][4][512]

    int b = blockIdx.y;
    const float* hp  = g_h2  + (size_t)b * NN * NC;
    const float* f1p = g_f1o + b * NN;
    const float* f2p = g_f2o + b * NN;
    const unsigned* ab = g_adjbits + (size_t)b * NN * 16;

    int t = threadIdx.x, w = t >> 5, lane = t & 31;

    {
        const float4* hp4 = (const float4*)hp;
        float4* hs4 = (float4*)hs;
        for (int i = t; i < NN * NC / 4; i += 256) hs4[i] = hp4[i];
        for (int i = t; i < NN; i += 256) f2s[i] = f2p[i];
    }
    __syncthreads();

    float* pw = ps + w * 4 * NN;

    for (int pass = blockIdx.x * 4; pass < blockIdx.x * 4 + 4; ++pass) {
        int r0 = pass * 32 + w * 4;
        float inv[4];
        __syncwarp();
#pragma unroll
        for (int r = 0; r < 4; ++r) {
            int row = r0 + r;
            float f1r = __ldg(&f1p[row]);
            const unsigned* abr = ab + row * 16;
            float ev[16];
            float mx = -3.4e38f;
#pragma unroll
            for (int it = 0; it < 16; ++it) {
                float e = f1r + f2s[lane + 32 * it];
                e = e > 0.f ? e : 0.2f * e;
                e = ((abr[it] >> lane) & 1u) ? e : -9e15f;
                ev[it] = e;
                mx = fmaxf(mx, e);
            }
#pragma unroll
            for (int o = 16; o; o >>= 1) mx = fmaxf(mx, __shfl_xor_sync(0xffffffffu, mx, o));
            float s = 0.f;
#pragma unroll
            for (int it = 0; it < 16; ++it) {
                float p = __expf(ev[it] - mx);
                s += p;
                pw[r * NN + lane + 32 * it] = p;
            }
#pragma unroll
            for (int o = 16; o; o >>= 1) s += __shfl_xor_sync(0xffffffffu, s, o);
            inv[r] = 1.f / s;
        }
        __syncwarp();

        float acc[4] = {0, 0, 0, 0};
        int c = lane & 15;
        int jb = (lane >> 4) * 256;
        for (int j = jb; j < jb + 256; ++j) {
            float hv = hs[j * NC + c];
            acc[0] = fmaf(pw[j], hv, acc[0]);
            acc[1] = fmaf(pw[NN + j], hv, acc[1]);
            acc[2] = fmaf(pw[2 * NN + j], hv, acc[2]);
            acc[3] = fmaf(pw[3 * NN + j], hv, acc[3]);
        }
#pragma unroll
        for (int r = 0; r < 4; ++r) acc[r] += __shfl_xor_sync(0xffffffffu, acc[r], 16);
        if (lane < 16) {
#pragma unroll
            for (int r = 0; r < 4; ++r)
                out_l2[((size_t)b * NN + (r0 + r)) * NC + c] = acc[r] * inv[r];
        }
    }
}

// ------------------------- launch ------------------------------------------
extern "C" void kernel_launch(void* const* d_in, const int* in_sizes, int n_in,
                              void* d_out, int out_size) {
    const float* x    = (const float*)d_in[0];
    const int*   adj  = (const int*)  d_in[1];
    const float* Wh   = (const float*)d_in[2];
    const float* a1h  = (const float*)d_in[3];
    const float* a2h  = (const float*)d_in[4];
    const float* Wout = (const float*)d_in[5];
    const float* a1o  = (const float*)d_in[6];
    const float* a2o  = (const float*)d_in[7];
    float* out = (float*)d_out;

    const int smem_gemm1 = (64 * XS_STRIDE + 128 * WS_STRIDE) * 4;               // 71680
    const int smem_attn1 = (NN * HS_STRIDE + 32 * PS_STRIDE + NN + 32) * 4;      // 216192
    const int smem_attn2 = (NN * NC + NN + 8 * 4 * NN) * 4;                      // 100352

    cudaFuncSetAttribute(gemm_heads, cudaFuncAttributeMaxDynamicSharedMemorySize, smem_gemm1);
    cudaFuncSetAttribute(attn1_kernel, cudaFuncAttributeMaxDynamicSharedMemorySize, smem_attn1);
    cudaFuncSetAttribute(attn_out, cudaFuncAttributeMaxDynamicSharedMemorySize, smem_attn2);

    adjbits_kernel<<<BATCH * NN / 8, 256>>>(adj);
    gemm_heads<<<dim3(8, NH, BATCH), 256, smem_gemm1>>>(x, Wh);
    f12_heads<<<BH, 256>>>(a1h, a2h);
    attn1_kernel<<<BH, 256, smem_attn1>>>();
    gemm_out<<<dim3(BATCH, 8), 256>>>(Wout);
    f12_out<<<BATCH, NN>>>(a1o, a2o);
    attn_out<<<dim3(4, BATCH), 256, smem_attn2>>>(out);
}

// round 4
// speedup vs baseline: 2.3208x; 1.3780x over previous
#include <cuda_runtime.h>
#include <cuda_bf16.h>
#include <cstdint>

// Problem constants
#define BATCH 32
#define NN    512       // nodes
#define NF    128       // input features
#define FH    64        // hidden per head
#define NH    8         // heads
#define NC    16        // classes
#define BH    (BATCH*NH)

// ------------------------- scratch (device globals, no allocs) -------------
__device__ float    g_h[BATCH*NH*NN*FH];     // head projections [b][h][n][64]
__device__ float    g_f1[BATCH*NH*NN];
__device__ float    g_f2[BATCH*NH*NN];
__device__ unsigned g_adjbits[BATCH*NN*16];  // 512 bits per row
__device__ float    g_xcat[BATCH*NN*NH*FH];  // layer-1 output (concat) [b][n][512]
__device__ float    g_h2[BATCH*NN*NC];       // output projection
__device__ float    g_f1o[BATCH*NN];
__device__ float    g_f2o[BATCH*NN];

// ------------------------- helpers -----------------------------------------
__device__ __forceinline__ float to_tf32(float v) {
    uint32_t b;
    asm("cvt.rna.tf32.f32 %0, %1;" : "=r"(b) : "f"(v));
    return __uint_as_float(b);
}
__device__ __forceinline__ uint32_t tf32_bits(float v) {
    uint32_t b;
    asm("cvt.rna.tf32.f32 %0, %1;" : "=r"(b) : "f"(v));
    return b;
}

__device__ __forceinline__ void mma_tf32(float d[4], const uint32_t a[4], const uint32_t b[2]) {
    asm volatile(
        "mma.sync.aligned.m16n8k8.row.col.f32.tf32.tf32.f32 "
        "{%0,%1,%2,%3}, {%4,%5,%6,%7}, {%8,%9}, {%0,%1,%2,%3};"
        : "+f"(d[0]), "+f"(d[1]), "+f"(d[2]), "+f"(d[3])
        : "r"(a[0]), "r"(a[1]), "r"(a[2]), "r"(a[3]), "r"(b[0]), "r"(b[1]));
}

// ------------------------- kernel 1: adjacency -> bitmask ------------------
__global__ void adjbits_kernel(const int* __restrict__ adj) {
    int w = threadIdx.x >> 5, lane = threadIdx.x & 31;
    int row = blockIdx.x * 8 + w;
    const int* ap = adj + (size_t)row * NN;
    unsigned* op = g_adjbits + row * 16;
#pragma unroll
    for (int it = 0; it < 16; ++it) {
        int v = ap[it * 32 + lane];
        unsigned m = __ballot_sync(0xffffffffu, v > 0);
        if (lane == 0) op[it] = m;
    }
}

// ------------------------- kernel 2: head projection GEMM (tf32 mma.sync) --
#define XS_STRIDE 136
#define WS_STRIDE 72
__global__ void __launch_bounds__(256) gemm_heads(const float* __restrict__ x,
                                                  const float* __restrict__ Wh) {
    extern __shared__ float sm[];
    float* xs = sm;
    float* Ws = sm + 64 * XS_STRIDE;
    int head = blockIdx.y, b = blockIdx.z;
    int n0 = blockIdx.x * 64;
    int t = threadIdx.x;

    const float4* xp4 = (const float4*)(x + ((size_t)b * NN + n0) * NF);
    for (int idx = t; idx < 64 * 32; idx += 256) {
        int r = idx >> 5, c4 = idx & 31;
        float4 v = xp4[idx];
        v.x = to_tf32(v.x); v.y = to_tf32(v.y); v.z = to_tf32(v.z); v.w = to_tf32(v.w);
        *(float4*)&xs[r * XS_STRIDE + c4 * 4] = v;
    }
    const float4* Wp4 = (const float4*)(Wh + (size_t)head * NF * FH);
    for (int idx = t; idx < 128 * 16; idx += 256) {
        int f = idx >> 4, o4 = idx & 15;
        float4 v = Wp4[idx];
        v.x = to_tf32(v.x); v.y = to_tf32(v.y); v.z = to_tf32(v.z); v.w = to_tf32(v.w);
        *(float4*)&Ws[f * WS_STRIDE + o4 * 4] = v;
    }
    __syncthreads();

    int w = t >> 5, lane = t & 31;
    int gid = lane >> 2, tig = lane & 3;
    int mt = w >> 1;
    int nbase = (w & 1) * 32;

    float d[4][4] = {};
    uint32_t a[4], bf[2];
#pragma unroll
    for (int kk = 0; kk < 16; ++kk) {
        int k0 = kk * 8;
        const float* pa = xs + (mt * 16 + gid) * XS_STRIDE + k0 + tig;
        a[0] = __float_as_uint(pa[0]);
        a[1] = __float_as_uint(pa[8 * XS_STRIDE]);
        a[2] = __float_as_uint(pa[4]);
        a[3] = __float_as_uint(pa[8 * XS_STRIDE + 4]);
#pragma unroll
        for (int nt = 0; nt < 4; ++nt) {
            const float* pb = Ws + (k0 + tig) * WS_STRIDE + nbase + nt * 8 + gid;
            bf[0] = __float_as_uint(pb[0]);
            bf[1] = __float_as_uint(pb[4 * WS_STRIDE]);
            mma_tf32(d[nt], a, bf);
        }
    }
    float* hp = g_h + (((size_t)b * NH + head) * NN + n0) * FH;
#pragma unroll
    for (int nt = 0; nt < 4; ++nt) {
        int col = nbase + nt * 8 + 2 * tig;
        int r0 = mt * 16 + gid;
        *(float2*)&hp[r0 * FH + col]       = make_float2(d[nt][0], d[nt][1]);
        *(float2*)&hp[(r0 + 8) * FH + col] = make_float2(d[nt][2], d[nt][3]);
    }
}

// ------------------------- kernel 3: f1/f2 per head ------------------------
__global__ void f12_heads(const float* __restrict__ a1, const float* __restrict__ a2) {
    int bh = blockIdx.x;
    int head = bh & 7;
    int w = threadIdx.x >> 5, lane = threadIdx.x & 31;
    float2 a1v = *(const float2*)&a1[head * FH + 2 * lane];
    float2 a2v = *(const float2*)&a2[head * FH + 2 * lane];
    const float* hp = g_h + (size_t)bh * NN * FH;
    for (int n = w; n < NN; n += 8) {
        float2 hv = *(const float2*)&hp[n * FH + 2 * lane];
        float s1 = hv.x * a1v.x + hv.y * a1v.y;
        float s2 = hv.x * a2v.x + hv.y * a2v.y;
#pragma unroll
        for (int o = 16; o; o >>= 1) {
            s1 += __shfl_xor_sync(0xffffffffu, s1, o);
            s2 += __shfl_xor_sync(0xffffffffu, s2, o);
        }
        if (lane == 0) {
            g_f1[bh * NN + n] = s1;
            g_f2[bh * NN + n] = s2;
        }
    }
}

// ------------------------- kernel 4: attn layer 1 (register-P + mma.sync) --
// One block per (b,head). h staged tf32 in smem [512][72] (conflict-free
// B frags). P never touches smem: each thread computes exactly the 4 A-frag
// values its MMA needs, from per-row (E1, E1n, -f1) and per-col (f2, e^f2,
// e^.2f2) tables — exp-product form of softmax numerator (no max-sub, no
// MUFU in loop). Row sums accumulate in the same registers; normalization +
// ELU in epilogue.
#define HS_STRIDE 72
#define A1_HS   0
#define A1_F2Q  (NN*HS_STRIDE*4)            // 147456
#define A1_F1T  (A1_F2Q + NN*16)            // 155648
#define A1_ABS  (A1_F1T + NN*16)            // 163840
#define ATTN1_SMEM (A1_ABS + NN*64)         // 196608

__global__ void __launch_bounds__(256) attn1_kernel() {
    extern __shared__ __align__(16) char smc[];
    float*    hs    = (float*)(smc + A1_HS);
    float4*   f2q   = (float4*)(smc + A1_F2Q);
    float4*   f1t   = (float4*)(smc + A1_F1T);
    unsigned* abs_s = (unsigned*)(smc + A1_ABS);

    int t = threadIdx.x, w = t >> 5, lane = t & 31;
    int gid = lane >> 2, tig = lane & 3;
    int blk = blockIdx.x, b = blk >> 3, head = blk & 7;
    const float* hp  = g_h  + (size_t)blk * NN * FH;
    const float* f1p = g_f1 + blk * NN;
    const float* f2p = g_f2 + blk * NN;
    const unsigned* ab = g_adjbits + (size_t)b * NN * 16;

    // ---- stage ----
    {
        const float4* hp4 = (const float4*)hp;
        for (int idx = t; idx < NN * 16; idx += 256) {
            int j = idx >> 4, c0 = (idx & 15) * 4;
            float4 v = hp4[idx];
            v.x = to_tf32(v.x); v.y = to_tf32(v.y); v.z = to_tf32(v.z); v.w = to_tf32(v.w);
            *(float4*)&hs[j * HS_STRIDE + c0] = v;
        }
        for (int i = t; i < NN; i += 256) {
            float f2 = f2p[i];
            f2q[i] = make_float4(f2, __expf(f2), __expf(0.2f * f2), 0.f);
            float f1 = f1p[i];
            f1t[i] = make_float4(__expf(f1), __expf(0.2f * f1), -f1, 0.f);
        }
        for (int i = t; i < NN * 16; i += 256) abs_s[i] = ab[i];
    }
    __syncthreads();

    for (int iter = 0; iter < 4; ++iter) {
        int r0 = (iter * 8 + w) * 16;
        int ra = r0 + gid, rb = ra + 8;
        float4 ta = f1t[ra];   // {E1, E1n, -f1, -}
        float4 tb = f1t[rb];
        const unsigned* ma = &abs_s[ra * 16];
        const unsigned* mb = &abs_s[rb * 16];

        float d[8][4];
#pragma unroll
        for (int nt = 0; nt < 8; ++nt)
#pragma unroll
            for (int u = 0; u < 4; ++u) d[nt][u] = 0.f;
        float rs0 = 0.f, rs1 = 0.f;

#pragma unroll 4
        for (int k0 = 0; k0 < NN; k0 += 8) {
            unsigned w0 = ma[k0 >> 5] >> ((k0 & 31) + tig);
            unsigned w1 = mb[k0 >> 5] >> ((k0 & 31) + tig);
            float4 q0 = f2q[k0 + tig];
            float4 q1 = f2q[k0 + tig + 4];

            float pa0 = (q0.x < ta.z) ? ta.y * q0.z : ta.x * q0.y;
            pa0 = (w0 & 1u) ? pa0 : 0.f;
            float pb0 = (q0.x < tb.z) ? tb.y * q0.z : tb.x * q0.y;
            pb0 = (w1 & 1u) ? pb0 : 0.f;
            float pa1 = (q1.x < ta.z) ? ta.y * q1.z : ta.x * q1.y;
            pa1 = ((w0 >> 4) & 1u) ? pa1 : 0.f;
            float pb1 = (q1.x < tb.z) ? tb.y * q1.z : tb.x * q1.y;
            pb1 = ((w1 >> 4) & 1u) ? pb1 : 0.f;

            rs0 += pa0 + pa1;
            rs1 += pb0 + pb1;

            uint32_t a[4];
            a[0] = tf32_bits(pa0);
            a[1] = tf32_bits(pb0);
            a[2] = tf32_bits(pa1);
            a[3] = tf32_bits(pb1);

            const float* pb = hs + (k0 + tig) * HS_STRIDE + gid;
#pragma unroll
            for (int nt = 0; nt < 8; ++nt) {
                uint32_t bf[2];
                bf[0] = __float_as_uint(pb[nt * 8]);
                bf[1] = __float_as_uint(pb[4 * HS_STRIDE + nt * 8]);
                mma_tf32(d[nt], a, bf);
            }
        }

        rs0 += __shfl_xor_sync(0xffffffffu, rs0, 1);
        rs0 += __shfl_xor_sync(0xffffffffu, rs0, 2);
        rs1 += __shfl_xor_sync(0xffffffffu, rs1, 1);
        rs1 += __shfl_xor_sync(0xffffffffu, rs1, 2);
        float inv0 = 1.f / rs0, inv1 = 1.f / rs1;

        float* oa = g_xcat + ((size_t)b * NN + ra) * (NH * FH) + head * FH;
        float* ob = g_xcat + ((size_t)b * NN + rb) * (NH * FH) + head * FH;
#pragma unroll
        for (int nt = 0; nt < 8; ++nt) {
            float v0 = d[nt][0] * inv0, v1 = d[nt][1] * inv0;
            v0 = v0 > 0.f ? v0 : (__expf(v0) - 1.f);
            v1 = v1 > 0.f ? v1 : (__expf(v1) - 1.f);
            *(float2*)&oa[nt * 8 + 2 * tig] = make_float2(v0, v1);
            float v2 = d[nt][2] * inv1, v3 = d[nt][3] * inv1;
            v2 = v2 > 0.f ? v2 : (__expf(v2) - 1.f);
            v3 = v3 > 0.f ? v3 : (__expf(v3) - 1.f);
            *(float2*)&ob[nt * 8 + 2 * tig] = make_float2(v2, v3);
        }
    }
}

// ------------------------- kernel 5: output projection GEMM ----------------
__global__ void __launch_bounds__(256) gemm_out(const float* __restrict__ Wout) {
    __shared__ float Ws[512 * 17];
    int b = blockIdx.x, rt = blockIdx.y;
    int t = threadIdx.x;
    for (int idx = t; idx < 512 * 16; idx += 256) {
        int k = idx >> 4, c = idx & 15;
        Ws[k * 17 + c] = Wout[idx];
    }
    __syncthreads();
    int w = t >> 5, lane = t & 31;
    int c = lane & 15;
    int k0 = (lane >> 4) * 256;
    for (int rr = w; rr < 64; rr += 8) {
        int row = rt * 64 + rr;
        const float* xp = g_xcat + ((size_t)b * NN + row) * 512;
        float acc = 0.f;
#pragma unroll 8
        for (int kk = 0; kk < 256; ++kk) {
            float xv = __ldg(&xp[k0 + kk]);
            acc = fmaf(xv, Ws[(k0 + kk) * 17 + c], acc);
        }
        acc += __shfl_xor_sync(0xffffffffu, acc, 16);
        if (lane < 16) g_h2[((size_t)b * NN + row) * NC + c] = acc;
    }
}

// ------------------------- kernel 6: f1/f2 for output layer ----------------
__global__ void f12_out(const float* __restrict__ a1o, const float* __restrict__ a2o) {
    int b = blockIdx.x;
    int n = threadIdx.x;
    const float* hp = g_h2 + ((size_t)b * NN + n) * NC;
    float s1 = 0.f, s2 = 0.f;
#pragma unroll
    for (int c = 0; c < NC; ++c) {
        float v = hp[c];
        s1 = fmaf(v, __ldg(&a1o[c]), s1);
        s2 = fmaf(v, __ldg(&a2o[c]), s2);
    }
    g_f1o[b * NN + n] = s1;
    g_f2o[b * NN + n] = s2;
}

// ------------------------- kernel 7: output attention (exp-product) --------
__global__ void __launch_bounds__(256) attn_out(float* __restrict__ out_l2) {
    extern __shared__ char sm2[];
    float*  hs  = (float*)sm2;                     // [512][16]
    float4* f2q = (float4*)(sm2 + 32768);          // [512] (f2, e^f2, e^.2f2, -)
    float*  ps  = (float*)(sm2 + 32768 + 8192);    // [8][4][512]

    int b = blockIdx.y;
    const float* hp  = g_h2  + (size_t)b * NN * NC;
    const float* f1p = g_f1o + b * NN;
    const float* f2p = g_f2o + b * NN;
    const unsigned* ab = g_adjbits + (size_t)b * NN * 16;

    int t = threadIdx.x, w = t >> 5, lane = t & 31;

    {
        const float4* hp4 = (const float4*)hp;
        float4* hs4 = (float4*)hs;
        for (int i = t; i < NN * NC / 4; i += 256) hs4[i] = hp4[i];
        for (int i = t; i < NN; i += 256) {
            float f2 = f2p[i];
            f2q[i] = make_float4(f2, __expf(f2), __expf(0.2f * f2), 0.f);
        }
    }
    __syncthreads();

    float* pw = ps + w * 4 * NN;

    for (int pass = blockIdx.x * 4; pass < blockIdx.x * 4 + 4; ++pass) {
        int r0 = pass * 32 + w * 4;
        float inv[4];
        __syncwarp();
#pragma unroll
        for (int r = 0; r < 4; ++r) {
            int row = r0 + r;
            float f1r = __ldg(&f1p[row]);
            float E1 = __expf(f1r), E1n = __expf(0.2f * f1r);
            const unsigned* abr = ab + row * 16;
            float s = 0.f;
#pragma unroll
            for (int it = 0; it < 16; ++it) {
                float4 fp = f2q[lane + 32 * it];
                float e = f1r + fp.x;
                float p = (e < 0.f) ? (E1n * fp.z) : (E1 * fp.y);
                p = ((abr[it] >> lane) & 1u) ? p : 0.f;
                s += p;
                pw[r * NN + lane + 32 * it] = p;
            }
#pragma unroll
            for (int o = 16; o; o >>= 1) s += __shfl_xor_sync(0xffffffffu, s, o);
            inv[r] = 1.f / s;
        }
        __syncwarp();

        float acc[4] = {0, 0, 0, 0};
        int c = lane & 15;
        int jb = (lane >> 4) * 256;
        for (int j = jb; j < jb + 256; ++j) {
            float hv = hs[j * NC + c];
            acc[0] = fmaf(pw[j], hv, acc[0]);
            acc[1] = fmaf(pw[NN + j], hv, acc[1]);
            acc[2] = fmaf(pw[2 * NN + j], hv, acc[2]);
            acc[3] = fmaf(pw[3 * NN + j], hv, acc[3]);
        }
#pragma unroll
        for (int r = 0; r < 4; ++r) acc[r] += __shfl_xor_sync(0xffffffffu, acc[r], 16);
        if (lane < 16) {
#pragma unroll
            for (int r = 0; r < 4; ++r)
                out_l2[((size_t)b * NN + (r0 + r)) * NC + c] = acc[r] * inv[r];
        }
    }
}

// ------------------------- launch ------------------------------------------
extern "C" void kernel_launch(void* const* d_in, const int* in_sizes, int n_in,
                              void* d_out, int out_size) {
    const float* x    = (const float*)d_in[0];
    const int*   adj  = (const int*)  d_in[1];
    const float* Wh   = (const float*)d_in[2];
    const float* a1h  = (const float*)d_in[3];
    const float* a2h  = (const float*)d_in[4];
    const float* Wout = (const float*)d_in[5];
    const float* a1o  = (const float*)d_in[6];
    const float* a2o  = (const float*)d_in[7];
    float* out = (float*)d_out;

    const int smem_gemm1 = (64 * XS_STRIDE + 128 * WS_STRIDE) * 4;
    const int smem_attn1 = ATTN1_SMEM;                   // 196608
    const int smem_attn2 = 32768 + 8192 + 65536;

    cudaFuncSetAttribute(gemm_heads, cudaFuncAttributeMaxDynamicSharedMemorySize, smem_gemm1);
    cudaFuncSetAttribute(attn1_kernel, cudaFuncAttributeMaxDynamicSharedMemorySize, smem_attn1);
    cudaFuncSetAttribute(attn_out, cudaFuncAttributeMaxDynamicSharedMemorySize, smem_attn2);

    adjbits_kernel<<<BATCH * NN / 8, 256>>>(adj);
    gemm_heads<<<dim3(8, NH, BATCH), 256, smem_gemm1>>>(x, Wh);
    f12_heads<<<BH, 256>>>(a1h, a2h);
    attn1_kernel<<<BH, 256, smem_attn1>>>();
    gemm_out<<<dim3(BATCH, 8), 256>>>(Wout);
    f12_out<<<BATCH, NN>>>(a1o, a2o);
    attn_out<<<dim3(4, BATCH), 256, smem_attn2>>>(out);
}

// round 5
// speedup vs baseline: 3.1489x; 1.3568x over previous
#include <cuda_runtime.h>
#include <cuda_bf16.h>
#include <cstdint>

// Problem constants
#define BATCH 32
#define NN    512       // nodes
#define NF    128       // input features
#define FH    64        // hidden per head
#define NH    8         // heads
#define NC    16        // classes
#define BH    (BATCH*NH)

// ------------------------- scratch (device globals, no allocs) -------------
__device__ float    g_h[BATCH*NH*NN*FH];     // head projections [b][h][n][64]
__device__ float    g_f1[BATCH*NH*NN];
__device__ float    g_f2[BATCH*NH*NN];
__device__ unsigned g_adjbits[BATCH*NN*16];  // 512 bits per row
__device__ float    g_xcat[BATCH*NN*NH*FH];  // layer-1 output [b][n][512]
__device__ float    g_h2[BATCH*NN*NC];       // output projection
__device__ float    g_f1o[BATCH*NN];
__device__ float    g_f2o[BATCH*NN];

// ------------------------- helpers -----------------------------------------
__device__ __forceinline__ float to_tf32(float v) {
    uint32_t b;
    asm("cvt.rna.tf32.f32 %0, %1;" : "=r"(b) : "f"(v));
    return __uint_as_float(b);
}
__device__ __forceinline__ uint32_t tf32_bits(float v) {
    uint32_t b;
    asm("cvt.rna.tf32.f32 %0, %1;" : "=r"(b) : "f"(v));
    return b;
}

__device__ __forceinline__ void mma_tf32(float d[4], const uint32_t a[4], const uint32_t b[2]) {
    asm volatile(
        "mma.sync.aligned.m16n8k8.row.col.f32.tf32.tf32.f32 "
        "{%0,%1,%2,%3}, {%4,%5,%6,%7}, {%8,%9}, {%0,%1,%2,%3};"
        : "+f"(d[0]), "+f"(d[1]), "+f"(d[2]), "+f"(d[3])
        : "r"(a[0]), "r"(a[1]), "r"(a[2]), "r"(a[3]), "r"(b[0]), "r"(b[1]));
}

// ------------------------- kernel 1: adjacency -> bitmask ------------------
__global__ void adjbits_kernel(const int* __restrict__ adj) {
    int w = threadIdx.x >> 5, lane = threadIdx.x & 31;
    int row = blockIdx.x * 8 + w;
    const int* ap = adj + (size_t)row * NN;
    unsigned* op = g_adjbits + row * 16;
#pragma unroll
    for (int it = 0; it < 16; ++it) {
        int v = ap[it * 32 + lane];
        unsigned m = __ballot_sync(0xffffffffu, v > 0);
        if (lane == 0) op[it] = m;
    }
}

// ------------------------- kernel 2: head GEMM + fused f1/f2 ---------------
#define XS_STRIDE 136
#define WS_STRIDE 72
#define GH_RED_OFF (64*XS_STRIDE + 128*WS_STRIDE)   // floats
#define GH_SMEM ((GH_RED_OFF + 256) * 4)

__global__ void __launch_bounds__(256) gemm_heads(const float* __restrict__ x,
                                                  const float* __restrict__ Wh,
                                                  const float* __restrict__ a1,
                                                  const float* __restrict__ a2) {
    extern __shared__ float sm[];
    float* xs = sm;
    float* Ws = sm + 64 * XS_STRIDE;
    float* sred = sm + GH_RED_OFF;      // [64][2 halves][2 f1f2]
    int head = blockIdx.y, b = blockIdx.z;
    int n0 = blockIdx.x * 64;
    int t = threadIdx.x;

    const float4* xp4 = (const float4*)(x + ((size_t)b * NN + n0) * NF);
    for (int idx = t; idx < 64 * 32; idx += 256) {
        int r = idx >> 5, c4 = idx & 31;
        float4 v = xp4[idx];
        v.x = to_tf32(v.x); v.y = to_tf32(v.y); v.z = to_tf32(v.z); v.w = to_tf32(v.w);
        *(float4*)&xs[r * XS_STRIDE + c4 * 4] = v;
    }
    const float4* Wp4 = (const float4*)(Wh + (size_t)head * NF * FH);
    for (int idx = t; idx < 128 * 16; idx += 256) {
        int f = idx >> 4, o4 = idx & 15;
        float4 v = Wp4[idx];
        v.x = to_tf32(v.x); v.y = to_tf32(v.y); v.z = to_tf32(v.z); v.w = to_tf32(v.w);
        *(float4*)&Ws[f * WS_STRIDE + o4 * 4] = v;
    }
    __syncthreads();

    int w = t >> 5, lane = t & 31;
    int gid = lane >> 2, tig = lane & 3;
    int mt = w >> 1;
    int nbase = (w & 1) * 32;

    float d[4][4] = {};
    uint32_t a[4], bf[2];
#pragma unroll
    for (int kk = 0; kk < 16; ++kk) {
        int k0 = kk * 8;
        const float* pa = xs + (mt * 16 + gid) * XS_STRIDE + k0 + tig;
        a[0] = __float_as_uint(pa[0]);
        a[1] = __float_as_uint(pa[8 * XS_STRIDE]);
        a[2] = __float_as_uint(pa[4]);
        a[3] = __float_as_uint(pa[8 * XS_STRIDE + 4]);
#pragma unroll
        for (int nt = 0; nt < 4; ++nt) {
            const float* pb = Ws + (k0 + tig) * WS_STRIDE + nbase + nt * 8 + gid;
            bf[0] = __float_as_uint(pb[0]);
            bf[1] = __float_as_uint(pb[4 * WS_STRIDE]);
            mma_tf32(d[nt], a, bf);
        }
    }
    float* hp = g_h + (((size_t)b * NH + head) * NN + n0) * FH;
#pragma unroll
    for (int nt = 0; nt < 4; ++nt) {
        int col = nbase + nt * 8 + 2 * tig;
        int r0 = mt * 16 + gid;
        *(float2*)&hp[r0 * FH + col]       = make_float2(d[nt][0], d[nt][1]);
        *(float2*)&hp[(r0 + 8) * FH + col] = make_float2(d[nt][2], d[nt][3]);
    }

    // fused f1/f2: dot this thread's cols with a1/a2, reduce over tig + halves
    float s1a = 0.f, s1b = 0.f, s2a = 0.f, s2b = 0.f;
#pragma unroll
    for (int nt = 0; nt < 4; ++nt) {
        int c0 = nbase + nt * 8 + 2 * tig;
        float a1x = __ldg(&a1[head * FH + c0]),     a1y = __ldg(&a1[head * FH + c0 + 1]);
        float a2x = __ldg(&a2[head * FH + c0]),     a2y = __ldg(&a2[head * FH + c0 + 1]);
        s1a += d[nt][0] * a1x + d[nt][1] * a1y;
        s1b += d[nt][2] * a1x + d[nt][3] * a1y;
        s2a += d[nt][0] * a2x + d[nt][1] * a2y;
        s2b += d[nt][2] * a2x + d[nt][3] * a2y;
    }
#pragma unroll
    for (int o = 1; o <= 2; o <<= 1) {
        s1a += __shfl_xor_sync(0xffffffffu, s1a, o);
        s1b += __shfl_xor_sync(0xffffffffu, s1b, o);
        s2a += __shfl_xor_sync(0xffffffffu, s2a, o);
        s2b += __shfl_xor_sync(0xffffffffu, s2b, o);
    }
    if (tig == 0) {
        int rl = mt * 16 + gid, hh = w & 1;
        sred[(rl)     * 4 + hh * 2 + 0] = s1a;
        sred[(rl)     * 4 + hh * 2 + 1] = s2a;
        sred[(rl + 8) * 4 + hh * 2 + 0] = s1b;
        sred[(rl + 8) * 4 + hh * 2 + 1] = s2b;
    }
    __syncthreads();
    if (t < 64) {
        int gi = ((size_t)0, ((b * NH + head) * NN + n0 + t));
        g_f1[gi] = sred[t * 4 + 0] + sred[t * 4 + 2];
        g_f2[gi] = sred[t * 4 + 1] + sred[t * 4 + 3];
    }
}

// ------------------------- kernel 3: attn layer 1 (register-P, 512 thr) ----
#define HS_STRIDE 72
#define A1_F2Q  (NN*HS_STRIDE*4)            // 147456
#define ATTN1_SMEM (A1_F2Q + NN*16)         // 155648

__global__ void __launch_bounds__(512) attn1_kernel() {
    extern __shared__ __align__(16) char smc[];
    float*  hs  = (float*)smc;
    float4* f2q = (float4*)(smc + A1_F2Q);

    int t = threadIdx.x, w = t >> 5, lane = t & 31;
    int gid = lane >> 2, tig = lane & 3;
    int blk = blockIdx.x, b = blk >> 3, head = blk & 7;
    const float* hp  = g_h  + (size_t)blk * NN * FH;
    const float* f1p = g_f1 + blk * NN;
    const float* f2p = g_f2 + blk * NN;
    const unsigned* ab = g_adjbits + (size_t)b * NN * 16;

    {
        const float4* hp4 = (const float4*)hp;
        for (int idx = t; idx < NN * 16; idx += 512) {
            int j = idx >> 4, c0 = (idx & 15) * 4;
            float4 v = hp4[idx];
            v.x = to_tf32(v.x); v.y = to_tf32(v.y); v.z = to_tf32(v.z); v.w = to_tf32(v.w);
            *(float4*)&hs[j * HS_STRIDE + c0] = v;
        }
        for (int i = t; i < NN; i += 512) {
            float f2 = f2p[i];
            f2q[i] = make_float4(f2, __expf(f2), __expf(0.2f * f2), 0.f);
        }
    }
    __syncthreads();

#pragma unroll
    for (int iter = 0; iter < 2; ++iter) {
        int r0 = (iter * 16 + w) * 16;
        int ra = r0 + gid, rb = ra + 8;
        float f1a = __ldg(&f1p[ra]), f1b = __ldg(&f1p[rb]);
        float Ea = __expf(f1a), Ean = __expf(0.2f * f1a), nfa = -f1a;
        float Eb = __expf(f1b), Ebn = __expf(0.2f * f1b), nfb = -f1b;
        const unsigned* ma = &ab[(size_t)ra * 16];
        const unsigned* mb = &ab[(size_t)rb * 16];

        float d[8][4];
#pragma unroll
        for (int nt = 0; nt < 8; ++nt)
#pragma unroll
            for (int u = 0; u < 4; ++u) d[nt][u] = 0.f;
        float rs0 = 0.f, rs1 = 0.f;

        for (int kw = 0; kw < 16; ++kw) {
            unsigned wa = __ldg(&ma[kw]) >> tig;
            unsigned wb = __ldg(&mb[kw]) >> tig;
#pragma unroll
            for (int ks = 0; ks < 4; ++ks) {
                int k0 = kw * 32 + ks * 8;
                unsigned w0 = wa >> (ks * 8);
                unsigned w1 = wb >> (ks * 8);
                float4 q0 = f2q[k0 + tig];
                float4 q1 = f2q[k0 + tig + 4];

                float pa0 = (q0.x < nfa) ? Ean * q0.z : Ea * q0.y;
                pa0 = (w0 & 1u) ? pa0 : 0.f;
                float pb0 = (q0.x < nfb) ? Ebn * q0.z : Eb * q0.y;
                pb0 = (w1 & 1u) ? pb0 : 0.f;
                float pa1 = (q1.x < nfa) ? Ean * q1.z : Ea * q1.y;
                pa1 = ((w0 >> 4) & 1u) ? pa1 : 0.f;
                float pb1 = (q1.x < nfb) ? Ebn * q1.z : Eb * q1.y;
                pb1 = ((w1 >> 4) & 1u) ? pb1 : 0.f;

                rs0 += pa0 + pa1;
                rs1 += pb0 + pb1;

                uint32_t a[4];
                a[0] = tf32_bits(pa0);
                a[1] = tf32_bits(pb0);
                a[2] = tf32_bits(pa1);
                a[3] = tf32_bits(pb1);

                const float* pb = hs + (k0 + tig) * HS_STRIDE + gid;
#pragma unroll
                for (int nt = 0; nt < 8; ++nt) {
                    uint32_t bf[2];
                    bf[0] = __float_as_uint(pb[nt * 8]);
                    bf[1] = __float_as_uint(pb[4 * HS_STRIDE + nt * 8]);
                    mma_tf32(d[nt], a, bf);
                }
            }
        }

        rs0 += __shfl_xor_sync(0xffffffffu, rs0, 1);
        rs0 += __shfl_xor_sync(0xffffffffu, rs0, 2);
        rs1 += __shfl_xor_sync(0xffffffffu, rs1, 1);
        rs1 += __shfl_xor_sync(0xffffffffu, rs1, 2);
        float inv0 = 1.f / rs0, inv1 = 1.f / rs1;

        float* oa = g_xcat + ((size_t)b * NN + ra) * (NH * FH) + head * FH;
        float* ob = g_xcat + ((size_t)b * NN + rb) * (NH * FH) + head * FH;
#pragma unroll
        for (int nt = 0; nt < 8; ++nt) {
            float v0 = d[nt][0] * inv0, v1 = d[nt][1] * inv0;
            v0 = v0 > 0.f ? v0 : (__expf(v0) - 1.f);
            v1 = v1 > 0.f ? v1 : (__expf(v1) - 1.f);
            *(float2*)&oa[nt * 8 + 2 * tig] = make_float2(v0, v1);
            float v2 = d[nt][2] * inv1, v3 = d[nt][3] * inv1;
            v2 = v2 > 0.f ? v2 : (__expf(v2) - 1.f);
            v3 = v3 > 0.f ? v3 : (__expf(v3) - 1.f);
            *(float2*)&ob[nt * 8 + 2 * tig] = make_float2(v2, v3);
        }
    }
}

// ------------------------- kernel 4: output GEMM + fused f1o/f2o -----------
__global__ void __launch_bounds__(256) gemm_out(const float* __restrict__ Wout,
                                                const float* __restrict__ a1o,
                                                const float* __restrict__ a2o) {
    __shared__ float Ws[512 * 17];
    int b = blockIdx.x, rt = blockIdx.y;
    int t = threadIdx.x;
    for (int idx = t; idx < 512 * 16; idx += 256) {
        int k = idx >> 4, c = idx & 15;
        Ws[k * 17 + c] = Wout[idx];
    }
    __syncthreads();
    int w = t >> 5, lane = t & 31;
    int c = lane & 15;
    int k0 = (lane >> 4) * 256;
    float a1c = __ldg(&a1o[c]), a2c = __ldg(&a2o[c]);
    for (int rr = w; rr < 64; rr += 8) {
        int row = rt * 64 + rr;
        const float* xp = g_xcat + ((size_t)b * NN + row) * 512;
        float acc = 0.f;
#pragma unroll 8
        for (int kk = 0; kk < 256; ++kk) {
            float xv = __ldg(&xp[k0 + kk]);
            acc = fmaf(xv, Ws[(k0 + kk) * 17 + c], acc);
        }
        acc += __shfl_xor_sync(0xffffffffu, acc, 16);
        if (lane < 16) g_h2[((size_t)b * NN + row) * NC + c] = acc;
        // fused f1o/f2o (lanes 16-31 mirror 0-15, each 16-group sums fully)
        float s1 = acc * a1c, s2 = acc * a2c;
#pragma unroll
        for (int o = 1; o <= 8; o <<= 1) {
            s1 += __shfl_xor_sync(0xffffffffu, s1, o);
            s2 += __shfl_xor_sync(0xffffffffu, s2, o);
        }
        if (lane == 0) {
            g_f1o[b * NN + row] = s1;
            g_f2o[b * NN + row] = s2;
        }
    }
}

// ------------------------- kernel 5: output attention (register-P MMA) -----
#define O_F2Q 32768
#define ATTN2_SMEM (O_F2Q + 8192)
__global__ void __launch_bounds__(256) attn_out(float* __restrict__ out_l2) {
    extern __shared__ __align__(16) char sm2[];
    float*  hs  = (float*)sm2;             // [512][16] swizzled
    float4* f2q = (float4*)(sm2 + O_F2Q);  // [512]

    int b = blockIdx.y, rbase = blockIdx.x * 128;
    const float* hp  = g_h2  + (size_t)b * NN * NC;
    const float* f1p = g_f1o + b * NN;
    const float* f2p = g_f2o + b * NN;
    const unsigned* ab = g_adjbits + (size_t)b * NN * 16;

    int t = threadIdx.x, w = t >> 5, lane = t & 31;
    int gid = lane >> 2, tig = lane & 3;

    for (int idx = t; idx < NN * NC; idx += 256) {
        int j = idx >> 4, c = idx & 15;
        hs[j * 16 + ((c + 4 * (j & 3)) & 15)] = to_tf32(hp[idx]);
    }
    for (int i = t; i < NN; i += 256) {
        float f2 = f2p[i];
        f2q[i] = make_float4(f2, __expf(f2), __expf(0.2f * f2), 0.f);
    }
    __syncthreads();

    int ra = rbase + w * 16 + gid, rb = ra + 8;
    float f1a = __ldg(&f1p[ra]), f1b = __ldg(&f1p[rb]);
    float Ea = __expf(f1a), Ean = __expf(0.2f * f1a), nfa = -f1a;
    float Eb = __expf(f1b), Ebn = __expf(0.2f * f1b), nfb = -f1b;
    const unsigned* ma = &ab[(size_t)ra * 16];
    const unsigned* mb = &ab[(size_t)rb * 16];
    int c0 = (gid + 4 * tig) & 15;           // swizzled col for nt=0
    int c1 = (c0 + 8) & 15;                  // swizzled col for nt=1

    float d[2][4] = {};
    float rs0 = 0.f, rs1 = 0.f;

    for (int kw = 0; kw < 16; ++kw) {
        unsigned wa = __ldg(&ma[kw]) >> tig;
        unsigned wb = __ldg(&mb[kw]) >> tig;
#pragma unroll
        for (int ks = 0; ks < 4; ++ks) {
            int k0 = kw * 32 + ks * 8;
            unsigned w0 = wa >> (ks * 8);
            unsigned w1 = wb >> (ks * 8);
            float4 q0 = f2q[k0 + tig];
            float4 q1 = f2q[k0 + tig + 4];

            float pa0 = (q0.x < nfa) ? Ean * q0.z : Ea * q0.y;
            pa0 = (w0 & 1u) ? pa0 : 0.f;
            float pb0 = (q0.x < nfb) ? Ebn * q0.z : Eb * q0.y;
            pb0 = (w1 & 1u) ? pb0 : 0.f;
            float pa1 = (q1.x < nfa) ? Ean * q1.z : Ea * q1.y;
            pa1 = ((w0 >> 4) & 1u) ? pa1 : 0.f;
            float pb1 = (q1.x < nfb) ? Ebn * q1.z : Eb * q1.y;
            pb1 = ((w1 >> 4) & 1u) ? pb1 : 0.f;

            rs0 += pa0 + pa1;
            rs1 += pb0 + pb1;

            uint32_t a[4];
            a[0] = tf32_bits(pa0);
            a[1] = tf32_bits(pb0);
            a[2] = tf32_bits(pa1);
            a[3] = tf32_bits(pb1);

            const float* pb0p = hs + (k0 + tig) * 16;
            const float* pb1p = hs + (k0 + tig + 4) * 16;
            uint32_t bf[2];
            bf[0] = __float_as_uint(pb0p[c0]);
            bf[1] = __float_as_uint(pb1p[c0]);
            mma_tf32(d[0], a, bf);
            bf[0] = __float_as_uint(pb0p[c1]);
            bf[1] = __float_as_uint(pb1p[c1]);
            mma_tf32(d[1], a, bf);
        }
    }

    rs0 += __shfl_xor_sync(0xffffffffu, rs0, 1);
    rs0 += __shfl_xor_sync(0xffffffffu, rs0, 2);
    rs1 += __shfl_xor_sync(0xffffffffu, rs1, 1);
    rs1 += __shfl_xor_sync(0xffffffffu, rs1, 2);
    float inv0 = 1.f / rs0, inv1 = 1.f / rs1;

    float* oa = out_l2 + ((size_t)b * NN + ra) * NC;
    float* ob = out_l2 + ((size_t)b * NN + rb) * NC;
#pragma unroll
    for (int nt = 0; nt < 2; ++nt) {
        *(float2*)&oa[nt * 8 + 2 * tig] = make_float2(d[nt][0] * inv0, d[nt][1] * inv0);
        *(float2*)&ob[nt * 8 + 2 * tig] = make_float2(d[nt][2] * inv1, d[nt][3] * inv1);
    }
}

// ------------------------- launch ------------------------------------------
extern "C" void kernel_launch(void* const* d_in, const int* in_sizes, int n_in,
                              void* d_out, int out_size) {
    const float* x    = (const float*)d_in[0];
    const int*   adj  = (const int*)  d_in[1];
    const float* Wh   = (const float*)d_in[2];
    const float* a1h  = (const float*)d_in[3];
    const float* a2h  = (const float*)d_in[4];
    const float* Wout = (const float*)d_in[5];
    const float* a1o  = (const float*)d_in[6];
    const float* a2o  = (const float*)d_in[7];
    float* out = (float*)d_out;

    cudaFuncSetAttribute(gemm_heads, cudaFuncAttributeMaxDynamicSharedMemorySize, GH_SMEM);
    cudaFuncSetAttribute(attn1_kernel, cudaFuncAttributeMaxDynamicSharedMemorySize, ATTN1_SMEM);
    cudaFuncSetAttribute(attn_out, cudaFuncAttributeMaxDynamicSharedMemorySize, ATTN2_SMEM);

    adjbits_kernel<<<BATCH * NN / 8, 256>>>(adj);
    gemm_heads<<<dim3(8, NH, BATCH), 256, GH_SMEM>>>(x, Wh, a1h, a2h);
    attn1_kernel<<<BH, 512, ATTN1_SMEM>>>();
    gemm_out<<<dim3(BATCH, 8), 256>>>(Wout, a1o, a2o);
    attn_out<<<dim3(4, BATCH), 256, ATTN2_SMEM>>>(out);
}

// round 6
// speedup vs baseline: 4.0711x; 1.2929x over previous
#include <cuda_runtime.h>
#include <cuda_bf16.h>
#include <cstdint>

// Problem constants
#define BATCH 32
#define NN    512       // nodes
#define NF    128       // input features
#define FH    64        // hidden per head
#define NH    8         // heads
#define NC    16        // classes
#define BH    (BATCH*NH)

// ------------------------- scratch (device globals, no allocs) -------------
__device__ float    g_h[BATCH*NH*NN*FH];     // head projections [b][h][n][64]
__device__ float    g_f1[BATCH*NH*NN];
__device__ float    g_f2[BATCH*NH*NN];
__device__ unsigned g_adjbits[BATCH*NN*16];  // 512 bits per row
__device__ float    g_xcat[BATCH*NN*NH*FH];  // layer-1 output [b][n][512]
__device__ float    g_h2[BATCH*NN*NC];       // output projection
__device__ float    g_f1o[BATCH*NN];
__device__ float    g_f2o[BATCH*NN];

// ------------------------- helpers -----------------------------------------
__device__ __forceinline__ float to_tf32(float v) {
    uint32_t b;
    asm("cvt.rna.tf32.f32 %0, %1;" : "=r"(b) : "f"(v));
    return __uint_as_float(b);
}
__device__ __forceinline__ uint32_t tf32_bits(float v) {
    uint32_t b;
    asm("cvt.rna.tf32.f32 %0, %1;" : "=r"(b) : "f"(v));
    return b;
}

__device__ __forceinline__ void mma_tf32(float d[4], const uint32_t a[4], const uint32_t b[2]) {
    asm volatile(
        "mma.sync.aligned.m16n8k8.row.col.f32.tf32.tf32.f32 "
        "{%0,%1,%2,%3}, {%4,%5,%6,%7}, {%8,%9}, {%0,%1,%2,%3};"
        : "+f"(d[0]), "+f"(d[1]), "+f"(d[2]), "+f"(d[3])
        : "r"(a[0]), "r"(a[1]), "r"(a[2]), "r"(a[3]), "r"(b[0]), "r"(b[1]));
}

// ------------------------- kernel 1: adjacency -> bitmask ------------------
__global__ void adjbits_kernel(const int* __restrict__ adj) {
    int w = threadIdx.x >> 5, lane = threadIdx.x & 31;
    int row = blockIdx.x * 8 + w;
    const int* ap = adj + (size_t)row * NN;
    unsigned* op = g_adjbits + row * 16;
#pragma unroll
    for (int it = 0; it < 16; ++it) {
        int v = ap[it * 32 + lane];
        unsigned m = __ballot_sync(0xffffffffu, v > 0);
        if (lane == 0) op[it] = m;
    }
}

// ------------------------- kernel 2: head GEMM + fused f1/f2 ---------------
#define XS_STRIDE 136
#define WS_STRIDE 72
#define GH_RED_OFF (64*XS_STRIDE + 128*WS_STRIDE)   // floats
#define GH_SMEM ((GH_RED_OFF + 256) * 4)

__global__ void __launch_bounds__(256) gemm_heads(const float* __restrict__ x,
                                                  const float* __restrict__ Wh,
                                                  const float* __restrict__ a1,
                                                  const float* __restrict__ a2) {
    extern __shared__ float sm[];
    float* xs = sm;
    float* Ws = sm + 64 * XS_STRIDE;
    float* sred = sm + GH_RED_OFF;      // [64][2 halves][2 f1f2]
    int head = blockIdx.y, b = blockIdx.z;
    int n0 = blockIdx.x * 64;
    int t = threadIdx.x;

    const float4* xp4 = (const float4*)(x + ((size_t)b * NN + n0) * NF);
    for (int idx = t; idx < 64 * 32; idx += 256) {
        int r = idx >> 5, c4 = idx & 31;
        float4 v = xp4[idx];
        v.x = to_tf32(v.x); v.y = to_tf32(v.y); v.z = to_tf32(v.z); v.w = to_tf32(v.w);
        *(float4*)&xs[r * XS_STRIDE + c4 * 4] = v;
    }
    const float4* Wp4 = (const float4*)(Wh + (size_t)head * NF * FH);
    for (int idx = t; idx < 128 * 16; idx += 256) {
        int f = idx >> 4, o4 = idx & 15;
        float4 v = Wp4[idx];
        v.x = to_tf32(v.x); v.y = to_tf32(v.y); v.z = to_tf32(v.z); v.w = to_tf32(v.w);
        *(float4*)&Ws[f * WS_STRIDE + o4 * 4] = v;
    }
    __syncthreads();

    int w = t >> 5, lane = t & 31;
    int gid = lane >> 2, tig = lane & 3;
    int mt = w >> 1;
    int nbase = (w & 1) * 32;

    float d[4][4] = {};
    uint32_t a[4], bf[2];
#pragma unroll
    for (int kk = 0; kk < 16; ++kk) {
        int k0 = kk * 8;
        const float* pa = xs + (mt * 16 + gid) * XS_STRIDE + k0 + tig;
        a[0] = __float_as_uint(pa[0]);
        a[1] = __float_as_uint(pa[8 * XS_STRIDE]);
        a[2] = __float_as_uint(pa[4]);
        a[3] = __float_as_uint(pa[8 * XS_STRIDE + 4]);
#pragma unroll
        for (int nt = 0; nt < 4; ++nt) {
            const float* pb = Ws + (k0 + tig) * WS_STRIDE + nbase + nt * 8 + gid;
            bf[0] = __float_as_uint(pb[0]);
            bf[1] = __float_as_uint(pb[4 * WS_STRIDE]);
            mma_tf32(d[nt], a, bf);
        }
    }
    float* hp = g_h + (((size_t)b * NH + head) * NN + n0) * FH;
#pragma unroll
    for (int nt = 0; nt < 4; ++nt) {
        int col = nbase + nt * 8 + 2 * tig;
        int r0 = mt * 16 + gid;
        *(float2*)&hp[r0 * FH + col]       = make_float2(d[nt][0], d[nt][1]);
        *(float2*)&hp[(r0 + 8) * FH + col] = make_float2(d[nt][2], d[nt][3]);
    }

    // fused f1/f2: dot this thread's cols with a1/a2, reduce over tig + halves
    float s1a = 0.f, s1b = 0.f, s2a = 0.f, s2b = 0.f;
#pragma unroll
    for (int nt = 0; nt < 4; ++nt) {
        int c0 = nbase + nt * 8 + 2 * tig;
        float a1x = __ldg(&a1[head * FH + c0]),     a1y = __ldg(&a1[head * FH + c0 + 1]);
        float a2x = __ldg(&a2[head * FH + c0]),     a2y = __ldg(&a2[head * FH + c0 + 1]);
        s1a += d[nt][0] * a1x + d[nt][1] * a1y;
        s1b += d[nt][2] * a1x + d[nt][3] * a1y;
        s2a += d[nt][0] * a2x + d[nt][1] * a2y;
        s2b += d[nt][2] * a2x + d[nt][3] * a2y;
    }
#pragma unroll
    for (int o = 1; o <= 2; o <<= 1) {
        s1a += __shfl_xor_sync(0xffffffffu, s1a, o);
        s1b += __shfl_xor_sync(0xffffffffu, s1b, o);
        s2a += __shfl_xor_sync(0xffffffffu, s2a, o);
        s2b += __shfl_xor_sync(0xffffffffu, s2b, o);
    }
    if (tig == 0) {
        int rl = mt * 16 + gid, hh = w & 1;
        sred[(rl)     * 4 + hh * 2 + 0] = s1a;
        sred[(rl)     * 4 + hh * 2 + 1] = s2a;
        sred[(rl + 8) * 4 + hh * 2 + 0] = s1b;
        sred[(rl + 8) * 4 + hh * 2 + 1] = s2b;
    }
    __syncthreads();
    if (t < 64) {
        int gi = (b * NH + head) * NN + n0 + t;
        g_f1[gi] = sred[t * 4 + 0] + sred[t * 4 + 2];
        g_f2[gi] = sred[t * 4 + 1] + sred[t * 4 + 3];
    }
}

// ------------------------- kernel 3: attn layer 1 (register-P, 512 thr) ----
#define HS_STRIDE 72
#define A1_F2Q  (NN*HS_STRIDE*4)            // 147456
#define ATTN1_SMEM (A1_F2Q + NN*16)         // 155648

__global__ void __launch_bounds__(512) attn1_kernel() {
    extern __shared__ __align__(16) char smc[];
    float*  hs  = (float*)smc;
    float4* f2q = (float4*)(smc + A1_F2Q);

    int t = threadIdx.x, w = t >> 5, lane = t & 31;
    int gid = lane >> 2, tig = lane & 3;
    int blk = blockIdx.x, b = blk >> 3, head = blk & 7;
    const float* hp  = g_h  + (size_t)blk * NN * FH;
    const float* f1p = g_f1 + blk * NN;
    const float* f2p = g_f2 + blk * NN;
    const unsigned* ab = g_adjbits + (size_t)b * NN * 16;

    {
        const float4* hp4 = (const float4*)hp;
        for (int idx = t; idx < NN * 16; idx += 512) {
            int j = idx >> 4, c0 = (idx & 15) * 4;
            float4 v = hp4[idx];
            v.x = to_tf32(v.x); v.y = to_tf32(v.y); v.z = to_tf32(v.z); v.w = to_tf32(v.w);
            *(float4*)&hs[j * HS_STRIDE + c0] = v;
        }
        for (int i = t; i < NN; i += 512) {
            float f2 = f2p[i];
            f2q[i] = make_float4(f2, __expf(f2), __expf(0.2f * f2), 0.f);
        }
    }
    __syncthreads();

#pragma unroll
    for (int iter = 0; iter < 2; ++iter) {
        int r0 = (iter * 16 + w) * 16;
        int ra = r0 + gid, rb = ra + 8;
        float f1a = __ldg(&f1p[ra]), f1b = __ldg(&f1p[rb]);
        float Ea = __expf(f1a), Ean = __expf(0.2f * f1a), nfa = -f1a;
        float Eb = __expf(f1b), Ebn = __expf(0.2f * f1b), nfb = -f1b;
        const unsigned* ma = &ab[(size_t)ra * 16];
        const unsigned* mb = &ab[(size_t)rb * 16];

        float d[8][4];
#pragma unroll
        for (int nt = 0; nt < 8; ++nt)
#pragma unroll
            for (int u = 0; u < 4; ++u) d[nt][u] = 0.f;
        float rs0 = 0.f, rs1 = 0.f;

        for (int kw = 0; kw < 16; ++kw) {
            unsigned wa = __ldg(&ma[kw]) >> tig;
            unsigned wb = __ldg(&mb[kw]) >> tig;
#pragma unroll
            for (int ks = 0; ks < 4; ++ks) {
                int k0 = kw * 32 + ks * 8;
                unsigned w0 = wa >> (ks * 8);
                unsigned w1 = wb >> (ks * 8);
                float4 q0 = f2q[k0 + tig];
                float4 q1 = f2q[k0 + tig + 4];

                float pa0 = (q0.x < nfa) ? Ean * q0.z : Ea * q0.y;
                pa0 = (w0 & 1u) ? pa0 : 0.f;
                float pb0 = (q0.x < nfb) ? Ebn * q0.z : Eb * q0.y;
                pb0 = (w1 & 1u) ? pb0 : 0.f;
                float pa1 = (q1.x < nfa) ? Ean * q1.z : Ea * q1.y;
                pa1 = ((w0 >> 4) & 1u) ? pa1 : 0.f;
                float pb1 = (q1.x < nfb) ? Ebn * q1.z : Eb * q1.y;
                pb1 = ((w1 >> 4) & 1u) ? pb1 : 0.f;

                rs0 += pa0 + pa1;
                rs1 += pb0 + pb1;

                uint32_t a[4];
                a[0] = tf32_bits(pa0);
                a[1] = tf32_bits(pb0);
                a[2] = tf32_bits(pa1);
                a[3] = tf32_bits(pb1);

                const float* pb = hs + (k0 + tig) * HS_STRIDE + gid;
#pragma unroll
                for (int nt = 0; nt < 8; ++nt) {
                    uint32_t bf[2];
                    bf[0] = __float_as_uint(pb[nt * 8]);
                    bf[1] = __float_as_uint(pb[4 * HS_STRIDE + nt * 8]);
                    mma_tf32(d[nt], a, bf);
                }
            }
        }

        rs0 += __shfl_xor_sync(0xffffffffu, rs0, 1);
        rs0 += __shfl_xor_sync(0xffffffffu, rs0, 2);
        rs1 += __shfl_xor_sync(0xffffffffu, rs1, 1);
        rs1 += __shfl_xor_sync(0xffffffffu, rs1, 2);
        float inv0 = 1.f / rs0, inv1 = 1.f / rs1;

        float* oa = g_xcat + ((size_t)b * NN + ra) * (NH * FH) + head * FH;
        float* ob = g_xcat + ((size_t)b * NN + rb) * (NH * FH) + head * FH;
#pragma unroll
        for (int nt = 0; nt < 8; ++nt) {
            float v0 = d[nt][0] * inv0, v1 = d[nt][1] * inv0;
            v0 = v0 > 0.f ? v0 : (__expf(v0) - 1.f);
            v1 = v1 > 0.f ? v1 : (__expf(v1) - 1.f);
            *(float2*)&oa[nt * 8 + 2 * tig] = make_float2(v0, v1);
            float v2 = d[nt][2] * inv1, v3 = d[nt][3] * inv1;
            v2 = v2 > 0.f ? v2 : (__expf(v2) - 1.f);
            v3 = v3 > 0.f ? v3 : (__expf(v3) - 1.f);
            *(float2*)&ob[nt * 8 + 2 * tig] = make_float2(v2, v3);
        }
    }
}

// ------------------------- kernel 4: output GEMM (tf32 MMA) + fused f1o/f2o
// 128-row x 16-col tile per block; x_cat chunked through smem (stride 68),
// Wout resident in smem (stride 24). Conflict-free A/B fragment loads.
#define GO_WS_STRIDE 24
#define GO_XS_STRIDE 68
#define GO_XS_OFF (512 * GO_WS_STRIDE)               // floats
#define GO_SMEM ((GO_XS_OFF + 128 * GO_XS_STRIDE) * 4)

__global__ void __launch_bounds__(256) gemm_out(const float* __restrict__ Wout,
                                                const float* __restrict__ a1o,
                                                const float* __restrict__ a2o) {
    extern __shared__ float sm[];
    float* Ws = sm;                    // [512][24]
    float* xs = sm + GO_XS_OFF;        // [128][68]
    int b = blockIdx.x, rt = blockIdx.y;
    int t = threadIdx.x, w = t >> 5, lane = t & 31;
    int gid = lane >> 2, tig = lane & 3;

    for (int idx = t; idx < 512 * 16; idx += 256) {
        int k = idx >> 4, c = idx & 15;
        Ws[k * GO_WS_STRIDE + c] = to_tf32(Wout[idx]);
    }

    const float4* xp4 = (const float4*)(g_xcat + ((size_t)b * NN + rt * 128) * 512);
    float d[2][4] = {};
    uint32_t a[4], bf[2];

#pragma unroll 1
    for (int ch = 0; ch < 8; ++ch) {
        __syncthreads();
        for (int idx = t; idx < 128 * 16; idx += 256) {
            int r = idx >> 4, c4 = idx & 15;
            float4 v = xp4[r * 128 + ch * 16 + c4];
            v.x = to_tf32(v.x); v.y = to_tf32(v.y); v.z = to_tf32(v.z); v.w = to_tf32(v.w);
            *(float4*)&xs[r * GO_XS_STRIDE + c4 * 4] = v;
        }
        __syncthreads();
        int m0 = w * 16;
#pragma unroll
        for (int ks = 0; ks < 8; ++ks) {
            int k0 = ks * 8;
            const float* pa = xs + (m0 + gid) * GO_XS_STRIDE + k0 + tig;
            a[0] = __float_as_uint(pa[0]);
            a[1] = __float_as_uint(pa[8 * GO_XS_STRIDE]);
            a[2] = __float_as_uint(pa[4]);
            a[3] = __float_as_uint(pa[8 * GO_XS_STRIDE + 4]);
            const float* pb = Ws + (ch * 64 + k0 + tig) * GO_WS_STRIDE + gid;
            bf[0] = __float_as_uint(pb[0]);
            bf[1] = __float_as_uint(pb[4 * GO_WS_STRIDE]);
            mma_tf32(d[0], a, bf);
            bf[0] = __float_as_uint(pb[8]);
            bf[1] = __float_as_uint(pb[4 * GO_WS_STRIDE + 8]);
            mma_tf32(d[1], a, bf);
        }
    }

    // write h2 + fused f1o/f2o
    int ra = rt * 128 + w * 16 + gid, rb = ra + 8;
    float* ha = g_h2 + ((size_t)b * NN + ra) * NC;
    float* hb = g_h2 + ((size_t)b * NN + rb) * NC;
    float s1a = 0.f, s1b = 0.f, s2a = 0.f, s2b = 0.f;
#pragma unroll
    for (int nt = 0; nt < 2; ++nt) {
        int c0 = nt * 8 + 2 * tig;
        *(float2*)&ha[c0] = make_float2(d[nt][0], d[nt][1]);
        *(float2*)&hb[c0] = make_float2(d[nt][2], d[nt][3]);
        float a1x = __ldg(&a1o[c0]), a1y = __ldg(&a1o[c0 + 1]);
        float a2x = __ldg(&a2o[c0]), a2y = __ldg(&a2o[c0 + 1]);
        s1a += d[nt][0] * a1x + d[nt][1] * a1y;
        s1b += d[nt][2] * a1x + d[nt][3] * a1y;
        s2a += d[nt][0] * a2x + d[nt][1] * a2y;
        s2b += d[nt][2] * a2x + d[nt][3] * a2y;
    }
#pragma unroll
    for (int o = 1; o <= 2; o <<= 1) {
        s1a += __shfl_xor_sync(0xffffffffu, s1a, o);
        s1b += __shfl_xor_sync(0xffffffffu, s1b, o);
        s2a += __shfl_xor_sync(0xffffffffu, s2a, o);
        s2b += __shfl_xor_sync(0xffffffffu, s2b, o);
    }
    if (tig == 0) {
        g_f1o[b * NN + ra] = s1a;
        g_f2o[b * NN + ra] = s2a;
        g_f1o[b * NN + rb] = s1b;
        g_f2o[b * NN + rb] = s2b;
    }
}

// ------------------------- kernel 5: output attention (register-P MMA) -----
#define O_F2Q 32768
#define ATTN2_SMEM (O_F2Q + 8192)
__global__ void __launch_bounds__(256) attn_out(float* __restrict__ out_l2) {
    extern __shared__ __align__(16) char sm2[];
    float*  hs  = (float*)sm2;             // [512][16] swizzled
    float4* f2q = (float4*)(sm2 + O_F2Q);  // [512]

    int b = blockIdx.y, rbase = blockIdx.x * 128;
    const float* hp  = g_h2  + (size_t)b * NN * NC;
    const float* f1p = g_f1o + b * NN;
    const float* f2p = g_f2o + b * NN;
    const unsigned* ab = g_adjbits + (size_t)b * NN * 16;

    int t = threadIdx.x, w = t >> 5, lane = t & 31;
    int gid = lane >> 2, tig = lane & 3;

    for (int idx = t; idx < NN * NC; idx += 256) {
        int j = idx >> 4, c = idx & 15;
        hs[j * 16 + ((c + 4 * (j & 3)) & 15)] = to_tf32(hp[idx]);
    }
    for (int i = t; i < NN; i += 256) {
        float f2 = f2p[i];
        f2q[i] = make_float4(f2, __expf(f2), __expf(0.2f * f2), 0.f);
    }
    __syncthreads();

    int ra = rbase + w * 16 + gid, rb = ra + 8;
    float f1a = __ldg(&f1p[ra]), f1b = __ldg(&f1p[rb]);
    float Ea = __expf(f1a), Ean = __expf(0.2f * f1a), nfa = -f1a;
    float Eb = __expf(f1b), Ebn = __expf(0.2f * f1b), nfb = -f1b;
    const unsigned* ma = &ab[(size_t)ra * 16];
    const unsigned* mb = &ab[(size_t)rb * 16];
    int c0 = (gid + 4 * tig) & 15;           // swizzled col for nt=0
    int c1 = (c0 + 8) & 15;                  // swizzled col for nt=1

    float d[2][4] = {};
    float rs0 = 0.f, rs1 = 0.f;

    for (int kw = 0; kw < 16; ++kw) {
        unsigned wa = __ldg(&ma[kw]) >> tig;
        unsigned wb = __ldg(&mb[kw]) >> tig;
#pragma unroll
        for (int ks = 0; ks < 4; ++ks) {
            int k0 = kw * 32 + ks * 8;
            unsigned w0 = wa >> (ks * 8);
            unsigned w1 = wb >> (ks * 8);
            float4 q0 = f2q[k0 + tig];
            float4 q1 = f2q[k0 + tig + 4];

            float pa0 = (q0.x < nfa) ? Ean * q0.z : Ea * q0.y;
            pa0 = (w0 & 1u) ? pa0 : 0.f;
            float pb0 = (q0.x < nfb) ? Ebn * q0.z : Eb * q0.y;
            pb0 = (w1 & 1u) ? pb0 : 0.f;
            float pa1 = (q1.x < nfa) ? Ean * q1.z : Ea * q1.y;
            pa1 = ((w0 >> 4) & 1u) ? pa1 : 0.f;
            float pb1 = (q1.x < nfb) ? Ebn * q1.z : Eb * q1.y;
            pb1 = ((w1 >> 4) & 1u) ? pb1 : 0.f;

            rs0 += pa0 + pa1;
            rs1 += pb0 + pb1;

            uint32_t a[4];
            a[0] = tf32_bits(pa0);
            a[1] = tf32_bits(pb0);
            a[2] = tf32_bits(pa1);
            a[3] = tf32_bits(pb1);

            const float* pb0p = hs + (k0 + tig) * 16;
            const float* pb1p = hs + (k0 + tig + 4) * 16;
            uint32_t bf[2];
            bf[0] = __float_as_uint(pb0p[c0]);
            bf[1] = __float_as_uint(pb1p[c0]);
            mma_tf32(d[0], a, bf);
            bf[0] = __float_as_uint(pb0p[c1]);
            bf[1] = __float_as_uint(pb1p[c1]);
            mma_tf32(d[1], a, bf);
        }
    }

    rs0 += __shfl_xor_sync(0xffffffffu, rs0, 1);
    rs0 += __shfl_xor_sync(0xffffffffu, rs0, 2);
    rs1 += __shfl_xor_sync(0xffffffffu, rs1, 1);
    rs1 += __shfl_xor_sync(0xffffffffu, rs1, 2);
    float inv0 = 1.f / rs0, inv1 = 1.f / rs1;

    float* oa = out_l2 + ((size_t)b * NN + ra) * NC;
    float* ob = out_l2 + ((size_t)b * NN + rb) * NC;
#pragma unroll
    for (int nt = 0; nt < 2; ++nt) {
        *(float2*)&oa[nt * 8 + 2 * tig] = make_float2(d[nt][0] * inv0, d[nt][1] * inv0);
        *(float2*)&ob[nt * 8 + 2 * tig] = make_float2(d[nt][2] * inv1, d[nt][3] * inv1);
    }
}

// ------------------------- launch ------------------------------------------
extern "C" void kernel_launch(void* const* d_in, const int* in_sizes, int n_in,
                              void* d_out, int out_size) {
    const float* x    = (const float*)d_in[0];
    const int*   adj  = (const int*)  d_in[1];
    const float* Wh   = (const float*)d_in[2];
    const float* a1h  = (const float*)d_in[3];
    const float* a2h  = (const float*)d_in[4];
    const float* Wout = (const float*)d_in[5];
    const float* a1o  = (const float*)d_in[6];
    const float* a2o  = (const float*)d_in[7];
    float* out = (float*)d_out;

    cudaFuncSetAttribute(gemm_heads, cudaFuncAttributeMaxDynamicSharedMemorySize, GH_SMEM);
    cudaFuncSetAttribute(attn1_kernel, cudaFuncAttributeMaxDynamicSharedMemorySize, ATTN1_SMEM);
    cudaFuncSetAttribute(gemm_out, cudaFuncAttributeMaxDynamicSharedMemorySize, GO_SMEM);
    cudaFuncSetAttribute(attn_out, cudaFuncAttributeMaxDynamicSharedMemorySize, ATTN2_SMEM);

    adjbits_kernel<<<BATCH * NN / 8, 256>>>(adj);
    gemm_heads<<<dim3(8, NH, BATCH), 256, GH_SMEM>>>(x, Wh, a1h, a2h);
    attn1_kernel<<<BH, 512, ATTN1_SMEM>>>();
    gemm_out<<<dim3(BATCH, 4), 256, GO_SMEM>>>(Wout, a1o, a2o);
    attn_out<<<dim3(4, BATCH), 256, ATTN2_SMEM>>>(out);
}

// round 7
// speedup vs baseline: 4.6304x; 1.1374x over previous
#include <cuda_runtime.h>
#include <cuda_bf16.h>
#include <cstdint>

// Problem constants
#define BATCH 32
#define NN    512       // nodes
#define NF    128       // input features
#define FH    64        // hidden per head
#define NH    8         // heads
#define NC    16        // classes
#define BH    (BATCH*NH)

// ------------------------- scratch (device globals, no allocs) -------------
__device__ float    g_h[BATCH*NH*NN*FH];     // head projections [b][h][n][64]
__device__ float    g_f1[BATCH*NH*NN];
__device__ float    g_f2[BATCH*NH*NN];
__device__ unsigned g_adjbits[BATCH*NN*16];  // 512 bits per row
__device__ float    g_xcat[BATCH*NN*NH*FH];  // layer-1 output [b][n][512]
__device__ float    g_h2[BATCH*NN*NC];       // output projection
__device__ float    g_f1o[BATCH*NN];
__device__ float    g_f2o[BATCH*NN];

// ------------------------- helpers -----------------------------------------
__device__ __forceinline__ float to_tf32(float v) {
    uint32_t b;
    asm("cvt.rna.tf32.f32 %0, %1;" : "=r"(b) : "f"(v));
    return __uint_as_float(b);
}
__device__ __forceinline__ uint32_t tf32_bits(float v) {
    uint32_t b;
    asm("cvt.rna.tf32.f32 %0, %1;" : "=r"(b) : "f"(v));
    return b;
}

__device__ __forceinline__ void mma_tf32(float d[4], const uint32_t a[4], const uint32_t b[2]) {
    asm volatile(
        "mma.sync.aligned.m16n8k8.row.col.f32.tf32.tf32.f32 "
        "{%0,%1,%2,%3}, {%4,%5,%6,%7}, {%8,%9}, {%0,%1,%2,%3};"
        : "+f"(d[0]), "+f"(d[1]), "+f"(d[2]), "+f"(d[3])
        : "r"(a[0]), "r"(a[1]), "r"(a[2]), "r"(a[3]), "r"(b[0]), "r"(b[1]));
}

__device__ __forceinline__ void cp_async16(uint32_t saddr, const void* g) {
    asm volatile("cp.async.cg.shared.global [%0], [%1], 16;" :: "r"(saddr), "l"(g));
}
#define CP_COMMIT() asm volatile("cp.async.commit_group;" ::: "memory")
#define CP_WAIT(n)  asm volatile("cp.async.wait_group %0;" :: "n"(n) : "memory")

// ------------------------- kernel 1: adjacency -> bitmask ------------------
__global__ void adjbits_kernel(const int* __restrict__ adj) {
    int w = threadIdx.x >> 5, lane = threadIdx.x & 31;
    int row = blockIdx.x * 8 + w;
    const int* ap = adj + (size_t)row * NN;
    unsigned* op = g_adjbits + row * 16;
#pragma unroll
    for (int it = 0; it < 16; ++it) {
        int v = ap[it * 32 + lane];
        unsigned m = __ballot_sync(0xffffffffu, v > 0);
        if (lane == 0) op[it] = m;
    }
}

// ------------------------- kernel 2: head GEMM (x resident, W pipelined) ---
// Block = 64-row x-tile for one b; loops all 8 heads. x staged once via
// cp.async; per-head W double-buffered with cp.async prefetch overlapping
// the current head's MMA. tf32 conversion at fragment-load time.
#define XS_STRIDE 136
#define WS_STRIDE 72
#define GH_WS_OFF  (64*XS_STRIDE)                  // floats
#define GH_RED_OFF (GH_WS_OFF + 2*128*WS_STRIDE)   // floats
#define GH_SMEM ((GH_RED_OFF + 256) * 4)

__global__ void __launch_bounds__(256) gemm_heads(const float* __restrict__ x,
                                                  const float* __restrict__ Wh,
                                                  const float* __restrict__ a1,
                                                  const float* __restrict__ a2) {
    extern __shared__ float sm[];
    float* xs = sm;                    // [64][136] raw fp32
    float* Wsb[2] = { sm + GH_WS_OFF, sm + GH_WS_OFF + 128 * WS_STRIDE };
    float* sred = sm + GH_RED_OFF;     // [64][2 nt-halves][2]
    int b = blockIdx.y;
    int n0 = blockIdx.x * 64;
    int t = threadIdx.x;
    uint32_t xs_u  = (uint32_t)__cvta_generic_to_shared(xs);
    uint32_t ws_u[2] = { (uint32_t)__cvta_generic_to_shared(Wsb[0]),
                         (uint32_t)__cvta_generic_to_shared(Wsb[1]) };

    // group0: x tile + W(head 0)
    const float4* xp4 = (const float4*)(x + ((size_t)b * NN + n0) * NF);
    for (int idx = t; idx < 64 * 32; idx += 256) {
        int r = idx >> 5, c4 = idx & 31;
        cp_async16(xs_u + (r * XS_STRIDE + c4 * 4) * 4, xp4 + idx);
    }
    const float4* Wp4 = (const float4*)Wh;   // [NH][128][16] float4
    for (int idx = t; idx < 128 * 16; idx += 256) {
        int f = idx >> 4, o4 = idx & 15;
        cp_async16(ws_u[0] + (f * WS_STRIDE + o4 * 4) * 4, Wp4 + idx);
    }
    CP_COMMIT();

    int w = t >> 5, lane = t & 31;
    int gid = lane >> 2, tig = lane & 3;
    int mt = w >> 1;
    int nbase = (w & 1) * 32;

#pragma unroll 1
    for (int head = 0; head < NH; ++head) {
        int buf = head & 1;
        if (head < NH - 1) {
            const float4* Wn = Wp4 + (size_t)(head + 1) * 128 * 16;
            for (int idx = t; idx < 128 * 16; idx += 256) {
                int f = idx >> 4, o4 = idx & 15;
                cp_async16(ws_u[buf ^ 1] + (f * WS_STRIDE + o4 * 4) * 4, Wn + idx);
            }
            CP_COMMIT();
            CP_WAIT(1);
        } else {
            CP_WAIT(0);
        }
        __syncthreads();

        const float* Ws = Wsb[buf];
        float d[4][4] = {};
        uint32_t a[4], bf[2];
#pragma unroll
        for (int kk = 0; kk < 16; ++kk) {
            int k0 = kk * 8;
            const float* pa = xs + (mt * 16 + gid) * XS_STRIDE + k0 + tig;
            a[0] = tf32_bits(pa[0]);
            a[1] = tf32_bits(pa[8 * XS_STRIDE]);
            a[2] = tf32_bits(pa[4]);
            a[3] = tf32_bits(pa[8 * XS_STRIDE + 4]);
#pragma unroll
            for (int nt = 0; nt < 4; ++nt) {
                const float* pb = Ws + (k0 + tig) * WS_STRIDE + nbase + nt * 8 + gid;
                bf[0] = tf32_bits(pb[0]);
                bf[1] = tf32_bits(pb[4 * WS_STRIDE]);
                mma_tf32(d[nt], a, bf);
            }
        }
        float* hp = g_h + (((size_t)b * NH + head) * NN + n0) * FH;
#pragma unroll
        for (int nt = 0; nt < 4; ++nt) {
            int col = nbase + nt * 8 + 2 * tig;
            int r0 = mt * 16 + gid;
            *(float2*)&hp[r0 * FH + col]       = make_float2(d[nt][0], d[nt][1]);
            *(float2*)&hp[(r0 + 8) * FH + col] = make_float2(d[nt][2], d[nt][3]);
        }

        // fused f1/f2
        float s1a = 0.f, s1b = 0.f, s2a = 0.f, s2b = 0.f;
#pragma unroll
        for (int nt = 0; nt < 4; ++nt) {
            int c0 = nbase + nt * 8 + 2 * tig;
            float a1x = __ldg(&a1[head * FH + c0]), a1y = __ldg(&a1[head * FH + c0 + 1]);
            float a2x = __ldg(&a2[head * FH + c0]), a2y = __ldg(&a2[head * FH + c0 + 1]);
            s1a += d[nt][0] * a1x + d[nt][1] * a1y;
            s1b += d[nt][2] * a1x + d[nt][3] * a1y;
            s2a += d[nt][0] * a2x + d[nt][1] * a2y;
            s2b += d[nt][2] * a2x + d[nt][3] * a2y;
        }
#pragma unroll
        for (int o = 1; o <= 2; o <<= 1) {
            s1a += __shfl_xor_sync(0xffffffffu, s1a, o);
            s1b += __shfl_xor_sync(0xffffffffu, s1b, o);
            s2a += __shfl_xor_sync(0xffffffffu, s2a, o);
            s2b += __shfl_xor_sync(0xffffffffu, s2b, o);
        }
        if (tig == 0) {
            int rl = mt * 16 + gid, hh = w & 1;
            sred[(rl)     * 4 + hh * 2 + 0] = s1a;
            sred[(rl)     * 4 + hh * 2 + 1] = s2a;
            sred[(rl + 8) * 4 + hh * 2 + 0] = s1b;
            sred[(rl + 8) * 4 + hh * 2 + 1] = s2b;
        }
        __syncthreads();
        if (t < 64) {
            int gi = (b * NH + head) * NN + n0 + t;
            g_f1[gi] = sred[t * 4 + 0] + sred[t * 4 + 2];
            g_f2[gi] = sred[t * 4 + 1] + sred[t * 4 + 3];
        }
    }
}

// ------------------------- kernel 3: attn layer 1 (register-P, 512 thr) ----
#define HS_STRIDE 72
#define A1_F2Q  (NN*HS_STRIDE*4)            // 147456
#define ATTN1_SMEM (A1_F2Q + NN*16)         // 155648

__global__ void __launch_bounds__(512) attn1_kernel() {
    extern __shared__ __align__(16) char smc[];
    float*  hs  = (float*)smc;
    float4* f2q = (float4*)(smc + A1_F2Q);

    int t = threadIdx.x, w = t >> 5, lane = t & 31;
    int gid = lane >> 2, tig = lane & 3;
    int blk = blockIdx.x, b = blk >> 3, head = blk & 7;
    const float* hp  = g_h  + (size_t)blk * NN * FH;
    const float* f1p = g_f1 + blk * NN;
    const float* f2p = g_f2 + blk * NN;
    const unsigned* ab = g_adjbits + (size_t)b * NN * 16;

    {
        const float4* hp4 = (const float4*)hp;
        for (int idx = t; idx < NN * 16; idx += 512) {
            int j = idx >> 4, c0 = (idx & 15) * 4;
            float4 v = hp4[idx];
            v.x = to_tf32(v.x); v.y = to_tf32(v.y); v.z = to_tf32(v.z); v.w = to_tf32(v.w);
            *(float4*)&hs[j * HS_STRIDE + c0] = v;
        }
        for (int i = t; i < NN; i += 512) {
            float f2 = f2p[i];
            f2q[i] = make_float4(f2, __expf(f2), __expf(0.2f * f2), 0.f);
        }
    }
    __syncthreads();

#pragma unroll
    for (int iter = 0; iter < 2; ++iter) {
        int r0 = (iter * 16 + w) * 16;
        int ra = r0 + gid, rb = ra + 8;
        float f1a = __ldg(&f1p[ra]), f1b = __ldg(&f1p[rb]);
        float Ea = __expf(f1a), Ean = __expf(0.2f * f1a), nfa = -f1a;
        float Eb = __expf(f1b), Ebn = __expf(0.2f * f1b), nfb = -f1b;
        const unsigned* ma = &ab[(size_t)ra * 16];
        const unsigned* mb = &ab[(size_t)rb * 16];

        float d[8][4];
#pragma unroll
        for (int nt = 0; nt < 8; ++nt)
#pragma unroll
            for (int u = 0; u < 4; ++u) d[nt][u] = 0.f;
        float rs0 = 0.f, rs1 = 0.f;

        for (int kw = 0; kw < 16; ++kw) {
            unsigned wa = __ldg(&ma[kw]) >> tig;
            unsigned wb = __ldg(&mb[kw]) >> tig;
#pragma unroll
            for (int ks = 0; ks < 4; ++ks) {
                int k0 = kw * 32 + ks * 8;
                unsigned w0 = wa >> (ks * 8);
                unsigned w1 = wb >> (ks * 8);
                float4 q0 = f2q[k0 + tig];
                float4 q1 = f2q[k0 + tig + 4];

                float pa0 = (q0.x < nfa) ? Ean * q0.z : Ea * q0.y;
                pa0 = (w0 & 1u) ? pa0 : 0.f;
                float pb0 = (q0.x < nfb) ? Ebn * q0.z : Eb * q0.y;
                pb0 = (w1 & 1u) ? pb0 : 0.f;
                float pa1 = (q1.x < nfa) ? Ean * q1.z : Ea * q1.y;
                pa1 = ((w0 >> 4) & 1u) ? pa1 : 0.f;
                float pb1 = (q1.x < nfb) ? Ebn * q1.z : Eb * q1.y;
                pb1 = ((w1 >> 4) & 1u) ? pb1 : 0.f;

                rs0 += pa0 + pa1;
                rs1 += pb0 + pb1;

                uint32_t a[4];
                a[0] = tf32_bits(pa0);
                a[1] = tf32_bits(pb0);
                a[2] = tf32_bits(pa1);
                a[3] = tf32_bits(pb1);

                const float* pb = hs + (k0 + tig) * HS_STRIDE + gid;
#pragma unroll
                for (int nt = 0; nt < 8; ++nt) {
                    uint32_t bf[2];
                    bf[0] = __float_as_uint(pb[nt * 8]);
                    bf[1] = __float_as_uint(pb[4 * HS_STRIDE + nt * 8]);
                    mma_tf32(d[nt], a, bf);
                }
            }
        }

        rs0 += __shfl_xor_sync(0xffffffffu, rs0, 1);
        rs0 += __shfl_xor_sync(0xffffffffu, rs0, 2);
        rs1 += __shfl_xor_sync(0xffffffffu, rs1, 1);
        rs1 += __shfl_xor_sync(0xffffffffu, rs1, 2);
        float inv0 = 1.f / rs0, inv1 = 1.f / rs1;

        float* oa = g_xcat + ((size_t)b * NN + ra) * (NH * FH) + head * FH;
        float* ob = g_xcat + ((size_t)b * NN + rb) * (NH * FH) + head * FH;
#pragma unroll
        for (int nt = 0; nt < 8; ++nt) {
            float v0 = d[nt][0] * inv0, v1 = d[nt][1] * inv0;
            v0 = v0 > 0.f ? v0 : (__expf(v0) - 1.f);
            v1 = v1 > 0.f ? v1 : (__expf(v1) - 1.f);
            *(float2*)&oa[nt * 8 + 2 * tig] = make_float2(v0, v1);
            float v2 = d[nt][2] * inv1, v3 = d[nt][3] * inv1;
            v2 = v2 > 0.f ? v2 : (__expf(v2) - 1.f);
            v3 = v3 > 0.f ? v3 : (__expf(v3) - 1.f);
            *(float2*)&ob[nt * 8 + 2 * tig] = make_float2(v2, v3);
        }
    }
}

// ------------------------- kernel 4: output GEMM (pipelined) + f1o/f2o -----
// 64-row x 16-col tile per block (grid 32x8). x_cat chunks double-buffered
// via cp.async; Wout staged raw; tf32 cvt at fragment load.
#define GO_WS_STRIDE 24
#define GO_XS_STRIDE 68
#define GO_XS_OFF  (512 * GO_WS_STRIDE)                       // floats
#define GO_RED_OFF (GO_XS_OFF + 2 * 64 * GO_XS_STRIDE)        // floats
#define GO_SMEM ((GO_RED_OFF + 256) * 4)

__global__ void __launch_bounds__(256) gemm_out(const float* __restrict__ Wout,
                                                const float* __restrict__ a1o,
                                                const float* __restrict__ a2o) {
    extern __shared__ float sm[];
    float* Ws = sm;                                   // [512][24]
    float* xsb[2] = { sm + GO_XS_OFF, sm + GO_XS_OFF + 64 * GO_XS_STRIDE };
    float* sred = sm + GO_RED_OFF;
    int b = blockIdx.x, rt = blockIdx.y;
    int t = threadIdx.x, w = t >> 5, lane = t & 31;
    int gid = lane >> 2, tig = lane & 3;
    uint32_t ws_u = (uint32_t)__cvta_generic_to_shared(Ws);
    uint32_t xs_u[2] = { (uint32_t)__cvta_generic_to_shared(xsb[0]),
                         (uint32_t)__cvta_generic_to_shared(xsb[1]) };

    const float4* Wo4 = (const float4*)Wout;          // [512][4] float4
    for (int idx = t; idx < 512 * 4; idx += 256) {
        int k = idx >> 2, c4 = idx & 3;
        cp_async16(ws_u + (k * GO_WS_STRIDE + c4 * 4) * 4, Wo4 + idx);
    }
    const float4* xp4 = (const float4*)(g_xcat + ((size_t)b * NN + rt * 64) * 512);
    for (int idx = t; idx < 64 * 16; idx += 256) {
        int r = idx >> 4, c4 = idx & 15;
        cp_async16(xs_u[0] + (r * GO_XS_STRIDE + c4 * 4) * 4, xp4 + r * 128 + c4);
    }
    CP_COMMIT();

    int mt = w >> 1, ntile = w & 1;
    float d[4] = {};
    uint32_t a[4], bf[2];

#pragma unroll 1
    for (int ch = 0; ch < 8; ++ch) {
        int buf = ch & 1;
        if (ch < 7) {
            for (int idx = t; idx < 64 * 16; idx += 256) {
                int r = idx >> 4, c4 = idx & 15;
                cp_async16(xs_u[buf ^ 1] + (r * GO_XS_STRIDE + c4 * 4) * 4,
                           xp4 + r * 128 + (ch + 1) * 16 + c4);
            }
            CP_COMMIT();
            CP_WAIT(1);
        } else {
            CP_WAIT(0);
        }
        __syncthreads();
        const float* xs = xsb[buf];
#pragma unroll
        for (int ks = 0; ks < 8; ++ks) {
            int k0 = ks * 8;
            const float* pa = xs + (mt * 16 + gid) * GO_XS_STRIDE + k0 + tig;
            a[0] = tf32_bits(pa[0]);
            a[1] = tf32_bits(pa[8 * GO_XS_STRIDE]);
            a[2] = tf32_bits(pa[4]);
            a[3] = tf32_bits(pa[8 * GO_XS_STRIDE + 4]);
            const float* pb = Ws + (ch * 64 + k0 + tig) * GO_WS_STRIDE + ntile * 8 + gid;
            bf[0] = tf32_bits(pb[0]);
            bf[1] = tf32_bits(pb[4 * GO_WS_STRIDE]);
            mma_tf32(d, a, bf);
        }
        __syncthreads();
    }

    // write h2 + fused f1o/f2o (cross-warp combine of the two n-tiles)
    int ra = rt * 64 + mt * 16 + gid, rb = ra + 8;
    int c0 = ntile * 8 + 2 * tig;
    *(float2*)&g_h2[((size_t)b * NN + ra) * NC + c0] = make_float2(d[0], d[1]);
    *(float2*)&g_h2[((size_t)b * NN + rb) * NC + c0] = make_float2(d[2], d[3]);

    float a1x = __ldg(&a1o[c0]), a1y = __ldg(&a1o[c0 + 1]);
    float a2x = __ldg(&a2o[c0]), a2y = __ldg(&a2o[c0 + 1]);
    float s1a = d[0] * a1x + d[1] * a1y;
    float s1b = d[2] * a1x + d[3] * a1y;
    float s2a = d[0] * a2x + d[1] * a2y;
    float s2b = d[2] * a2x + d[3] * a2y;
#pragma unroll
    for (int o = 1; o <= 2; o <<= 1) {
        s1a += __shfl_xor_sync(0xffffffffu, s1a, o);
        s1b += __shfl_xor_sync(0xffffffffu, s1b, o);
        s2a += __shfl_xor_sync(0xffffffffu, s2a, o);
        s2b += __shfl_xor_sync(0xffffffffu, s2b, o);
    }
    if (tig == 0) {
        int rl = mt * 16 + gid;
        sred[(rl)     * 4 + ntile * 2 + 0] = s1a;
        sred[(rl)     * 4 + ntile * 2 + 1] = s2a;
        sred[(rl + 8) * 4 + ntile * 2 + 0] = s1b;
        sred[(rl + 8) * 4 + ntile * 2 + 1] = s2b;
    }
    __syncthreads();
    if (t < 64) {
        g_f1o[b * NN + rt * 64 + t] = sred[t * 4 + 0] + sred[t * 4 + 2];
        g_f2o[b * NN + rt * 64 + t] = sred[t * 4 + 1] + sred[t * 4 + 3];
    }
}

// ------------------------- kernel 5: output attention (register-P MMA) -----
#define O_F2Q 32768
#define ATTN2_SMEM (O_F2Q + 8192)
__global__ void __launch_bounds__(256) attn_out(float* __restrict__ out_l2) {
    extern __shared__ __align__(16) char sm2[];
    float*  hs  = (float*)sm2;             // [512][16] swizzled
    float4* f2q = (float4*)(sm2 + O_F2Q);  // [512]

    int b = blockIdx.y, rbase = blockIdx.x * 128;
    const float* hp  = g_h2  + (size_t)b * NN * NC;
    const float* f1p = g_f1o + b * NN;
    const float* f2p = g_f2o + b * NN;
    const unsigned* ab = g_adjbits + (size_t)b * NN * 16;

    int t = threadIdx.x, w = t >> 5, lane = t & 31;
    int gid = lane >> 2, tig = lane & 3;

    for (int idx = t; idx < NN * NC; idx += 256) {
        int j = idx >> 4, c = idx & 15;
        hs[j * 16 + ((c + 4 * (j & 3)) & 15)] = to_tf32(hp[idx]);
    }
    for (int i = t; i < NN; i += 256) {
        float f2 = f2p[i];
        f2q[i] = make_float4(f2, __expf(f2), __expf(0.2f * f2), 0.f);
    }
    __syncthreads();

    int ra = rbase + w * 16 + gid, rb = ra + 8;
    float f1a = __ldg(&f1p[ra]), f1b = __ldg(&f1p[rb]);
    float Ea = __expf(f1a), Ean = __expf(0.2f * f1a), nfa = -f1a;
    float Eb = __expf(f1b), Ebn = __expf(0.2f * f1b), nfb = -f1b;
    const unsigned* ma = &ab[(size_t)ra * 16];
    const unsigned* mb = &ab[(size_t)rb * 16];
    int c0 = (gid + 4 * tig) & 15;           // swizzled col for nt=0
    int c1 = (c0 + 8) & 15;                  // swizzled col for nt=1

    float d[2][4] = {};
    float rs0 = 0.f, rs1 = 0.f;

    for (int kw = 0; kw < 16; ++kw) {
        unsigned wa = __ldg(&ma[kw]) >> tig;
        unsigned wb = __ldg(&mb[kw]) >> tig;
#pragma unroll
        for (int ks = 0; ks < 4; ++ks) {
            int k0 = kw * 32 + ks * 8;
            unsigned w0 = wa >> (ks * 8);
            unsigned w1 = wb >> (ks * 8);
            float4 q0 = f2q[k0 + tig];
            float4 q1 = f2q[k0 + tig + 4];

            float pa0 = (q0.x < nfa) ? Ean * q0.z : Ea * q0.y;
            pa0 = (w0 & 1u) ? pa0 : 0.f;
            float pb0 = (q0.x < nfb) ? Ebn * q0.z : Eb * q0.y;
            pb0 = (w1 & 1u) ? pb0 : 0.f;
            float pa1 = (q1.x < nfa) ? Ean * q1.z : Ea * q1.y;
            pa1 = ((w0 >> 4) & 1u) ? pa1 : 0.f;
            float pb1 = (q1.x < nfb) ? Ebn * q1.z : Eb * q1.y;
            pb1 = ((w1 >> 4) & 1u) ? pb1 : 0.f;

            rs0 += pa0 + pa1;
            rs1 += pb0 + pb1;

            uint32_t a[4];
            a[0] = tf32_bits(pa0);
            a[1] = tf32_bits(pb0);
            a[2] = tf32_bits(pa1);
            a[3] = tf32_bits(pb1);

            const float* pb0p = hs + (k0 + tig) * 16;
            const float* pb1p = hs + (k0 + tig + 4) * 16;
            uint32_t bf[2];
            bf[0] = __float_as_uint(pb0p[c0]);
            bf[1] = __float_as_uint(pb1p[c0]);
            mma_tf32(d[0], a, bf);
            bf[0] = __float_as_uint(pb0p[c1]);
            bf[1] = __float_as_uint(pb1p[c1]);
            mma_tf32(d[1], a, bf);
        }
    }

    rs0 += __shfl_xor_sync(0xffffffffu, rs0, 1);
    rs0 += __shfl_xor_sync(0xffffffffu, rs0, 2);
    rs1 += __shfl_xor_sync(0xffffffffu, rs1, 1);
    rs1 += __shfl_xor_sync(0xffffffffu, rs1, 2);
    float inv0 = 1.f / rs0, inv1 = 1.f / rs1;

    float* oa = out_l2 + ((size_t)b * NN + ra) * NC;
    float* ob = out_l2 + ((size_t)b * NN + rb) * NC;
#pragma unroll
    for (int nt = 0; nt < 2; ++nt) {
        *(float2*)&oa[nt * 8 + 2 * tig] = make_float2(d[nt][0] * inv0, d[nt][1] * inv0);
        *(float2*)&ob[nt * 8 + 2 * tig] = make_float2(d[nt][2] * inv1, d[nt][3] * inv1);
    }
}

// ------------------------- launch ------------------------------------------
extern "C" void kernel_launch(void* const* d_in, const int* in_sizes, int n_in,
                              void* d_out, int out_size) {
    const float* x    = (const float*)d_in[0];
    const int*   adj  = (const int*)  d_in[1];
    const float* Wh   = (const float*)d_in[2];
    const float* a1h  = (const float*)d_in[3];
    const float* a2h  = (const float*)d_in[4];
    const float* Wout = (const float*)d_in[5];
    const float* a1o  = (const float*)d_in[6];
    const float* a2o  = (const float*)d_in[7];
    float* out = (float*)d_out;

    cudaFuncSetAttribute(gemm_heads, cudaFuncAttributeMaxDynamicSharedMemorySize, GH_SMEM);
    cudaFuncSetAttribute(attn1_kernel, cudaFuncAttributeMaxDynamicSharedMemorySize, ATTN1_SMEM);
    cudaFuncSetAttribute(gemm_out, cudaFuncAttributeMaxDynamicSharedMemorySize, GO_SMEM);
    cudaFuncSetAttribute(attn_out, cudaFuncAttributeMaxDynamicSharedMemorySize, ATTN2_SMEM);

    adjbits_kernel<<<BATCH * NN / 8, 256>>>(adj);
    gemm_heads<<<dim3(8, BATCH), 256, GH_SMEM>>>(x, Wh, a1h, a2h);
    attn1_kernel<<<BH, 512, ATTN1_SMEM>>>();
    gemm_out<<<dim3(BATCH, 8), 256, GO_SMEM>>>(Wout, a1o, a2o);
    attn_out<<<dim3(4, BATCH), 256, ATTN2_SMEM>>>(out);
}